// round 2
// baseline (speedup 1.0000x reference)
#include <cuda_runtime.h>
#include <cuda_bf16.h>
#include <cstddef>

// ---------------- Problem constants ----------------
#define BB 4
#define SS 2048
#define DD 1024
#define HH 16
#define HD 64
#define LL 4
#define WIN 256
#define MT (BB*SS)          // 8192 rows
#define D4 (4*DD)           // 4096

// ---------------- Scratch (device globals; no allocation) ----------------
__device__ float g_x [MT*DD];
__device__ float g_h [MT*DD];
__device__ float g_q [MT*DD];
__device__ float g_k [MT*DD];
__device__ float g_v [MT*DD];
__device__ float g_o [MT*DD];
__device__ float g_m1[MT*D4];

// ---------------- packed f32x2 helpers (Blackwell) ----------------
typedef unsigned long long ull;

__device__ __forceinline__ ull fma2(ull a, ull b, ull c){
    ull d;
    asm("fma.rn.f32x2 %0, %1, %2, %3;" : "=l"(d) : "l"(a), "l"(b), "l"(c));
    return d;
}
__device__ __forceinline__ ull rep2(float x){
    ull r; unsigned u = __float_as_uint(x);
    asm("mov.b64 %0, {%1, %1};" : "=l"(r) : "r"(u));
    return r;
}
__device__ __forceinline__ float lo32(ull v){ return __uint_as_float((unsigned)v); }
__device__ __forceinline__ float hi32(ull v){ return __uint_as_float((unsigned)(v >> 32)); }

// ---------------- GEMM: C[M,N] = epi(A[M,K] @ B) (+residual) ----------------
// BT=false: B is [K,N] row-major.  BT=true: B is [N,K] row-major (C = A @ B^T).
#define GBM 128
#define GBN 128
#define GBK 16
#define GPAD 4
#define GST (GBM + GPAD)     // 132 floats smem row stride

enum { EPI_NONE = 0, EPI_SILU = 1, EPI_RESID = 2, EPI_TANH = 3 };

template<int EPI, bool BT>
__global__ __launch_bounds__(256, 2)
void gemm_k(const float* __restrict__ A, const float* __restrict__ B,
            const float* R, float* C, int N, int K)
{
    __shared__ float As[GBK][GST];
    __shared__ float Bs[GBK][GST];

    const int tid = threadIdx.x;
    const int m0 = blockIdx.y * GBM;
    const int n0 = blockIdx.x * GBN;
    const int tx = tid & 15;        // n-tile:  cols tx*8 .. +7
    const int ty = tid >> 4;        // m-tile:  rows ty*8 .. +7

    ull acc[8][4];
    #pragma unroll
    for (int i = 0; i < 8; i++)
        #pragma unroll
        for (int j = 0; j < 4; j++) acc[i][j] = 0ull;

    for (int kt = 0; kt < K; kt += GBK) {
        // ---- load A tile (128x16) transposed into As[k][m] ----
        #pragma unroll
        for (int i = 0; i < 2; i++) {
            int li  = tid + i * 256;          // 0..511 float4s
            int row = li >> 2;
            int c4  = (li & 3) * 4;
            float4 v = *(const float4*)(A + (size_t)(m0 + row) * K + kt + c4);
            As[c4 + 0][row] = v.x; As[c4 + 1][row] = v.y;
            As[c4 + 2][row] = v.z; As[c4 + 3][row] = v.w;
        }
        // ---- load B tile into Bs[k][n] ----
        if (!BT) {
            #pragma unroll
            for (int i = 0; i < 2; i++) {
                int li  = tid + i * 256;
                int row = li >> 5;            // 0..15
                int c4  = (li & 31) * 4;      // 0..124
                float4 v = *(const float4*)(B + (size_t)(kt + row) * N + n0 + c4);
                *(float4*)&Bs[row][c4] = v;
            }
        } else {
            #pragma unroll
            for (int i = 0; i < 2; i++) {
                int li  = tid + i * 256;
                int row = li >> 2;            // n-row 0..127
                int c4  = (li & 3) * 4;
                float4 v = *(const float4*)(B + (size_t)(n0 + row) * K + kt + c4);
                Bs[c4 + 0][row] = v.x; Bs[c4 + 1][row] = v.y;
                Bs[c4 + 2][row] = v.z; Bs[c4 + 3][row] = v.w;
            }
        }
        __syncthreads();

        #pragma unroll
        for (int kk = 0; kk < GBK; kk++) {
            float a[8];
            *(float4*)&a[0] = *(const float4*)&As[kk][ty * 8];
            *(float4*)&a[4] = *(const float4*)&As[kk][ty * 8 + 4];
            ull b[4];
            b[0] = *(const ull*)&Bs[kk][tx * 8 + 0];
            b[1] = *(const ull*)&Bs[kk][tx * 8 + 2];
            b[2] = *(const ull*)&Bs[kk][tx * 8 + 4];
            b[3] = *(const ull*)&Bs[kk][tx * 8 + 6];
            #pragma unroll
            for (int mi = 0; mi < 8; mi++) {
                ull ar = rep2(a[mi]);
                #pragma unroll
                for (int nj = 0; nj < 4; nj++)
                    acc[mi][nj] = fma2(ar, b[nj], acc[mi][nj]);
            }
        }
        __syncthreads();
    }

    // ---- epilogue ----
    #pragma unroll
    for (int mi = 0; mi < 8; mi++) {
        float o[8];
        #pragma unroll
        for (int nj = 0; nj < 4; nj++) {
            o[2 * nj]     = lo32(acc[mi][nj]);
            o[2 * nj + 1] = hi32(acc[mi][nj]);
        }
        size_t off = (size_t)(m0 + ty * 8 + mi) * N + n0 + tx * 8;
        if (EPI == EPI_SILU) {
            #pragma unroll
            for (int e = 0; e < 8; e++) o[e] = o[e] / (1.0f + __expf(-o[e]));
        } else if (EPI == EPI_RESID) {
            float4 r0 = *(const float4*)(R + off);
            float4 r1 = *(const float4*)(R + off + 4);
            o[0] += r0.x; o[1] += r0.y; o[2] += r0.z; o[3] += r0.w;
            o[4] += r1.x; o[5] += r1.y; o[6] += r1.z; o[7] += r1.w;
        } else if (EPI == EPI_TANH) {
            #pragma unroll
            for (int e = 0; e < 8; e++) o[e] = tanhf(o[e]);
        }
        *(float4*)(C + off)     = make_float4(o[0], o[1], o[2], o[3]);
        *(float4*)(C + off + 4) = make_float4(o[4], o[5], o[6], o[7]);
    }
}

// ---------------- RMSNorm (row-wise over D=1024) ----------------
__global__ __launch_bounds__(256) void rmsnorm_k(const float* __restrict__ X,
                                                 float* __restrict__ H)
{
    __shared__ float red[8];
    const int row = blockIdx.x;
    const int tid = threadIdx.x;
    const float4* x4 = (const float4*)(X + (size_t)row * DD);
    float4 v = x4[tid];
    float s = v.x * v.x + v.y * v.y + v.z * v.z + v.w * v.w;
    #pragma unroll
    for (int o = 16; o; o >>= 1) s += __shfl_xor_sync(0xffffffffu, s, o);
    if ((tid & 31) == 0) red[tid >> 5] = s;
    __syncthreads();
    float tot = red[0] + red[1] + red[2] + red[3] + red[4] + red[5] + red[6] + red[7];
    float inv = rsqrtf(tot * (1.0f / DD) + 1e-6f);
    float4 o;
    o.x = v.x * inv; o.y = v.y * inv; o.z = v.z * inv; o.w = v.w * inv;
    ((float4*)(H + (size_t)row * DD))[tid] = o;
}

// ---------------- RoPE (in-place on q or k, pair-safe) ----------------
__global__ __launch_bounds__(256) void rope_k(float* __restrict__ Q,
                                              const float* __restrict__ CO,
                                              const float* __restrict__ SI)
{
    int idx = blockIdx.x * blockDim.x + threadIdx.x;   // B*S*H*32 = 4194304 threads
    int d    = idx & 31;
    int rest = idx >> 5;
    int h    = rest & 15;
    int s    = (rest >> 4) & (SS - 1);
    int b    = rest >> 15;
    size_t base = ((size_t)(b * SS + s) * HH + h) * HD;
    float x1 = Q[base + d];
    float x2 = Q[base + d + 32];
    float c1 = CO[s * HD + d],      s1 = SI[s * HD + d];
    float c2 = CO[s * HD + d + 32], s2 = SI[s * HD + d + 32];
    Q[base + d]      = x1 * c1 - x2 * s1;
    Q[base + d + 32] = x2 * c2 + x1 * s2;
}

// ---------------- Sliding-window attention (flash-style) ----------------
// Layouts: q/k/v/o are [B,S,H,HD] contiguous (== [BS, D]).
#define ABR 32
#define ABC 64

__global__ __launch_bounds__(256) void attn_k(const float* __restrict__ Q,
                                              const float* __restrict__ K,
                                              const float* __restrict__ V,
                                              float* __restrict__ O)
{
    __shared__ float Qs[ABR][64];
    __shared__ float Ks[ABC][65];
    __shared__ float Vs[ABC][64];
    __shared__ float Ps[8][64];

    const int tid  = threadIdx.x;
    const int warp = tid >> 5;
    const int lane = tid & 31;
    const int bh = blockIdx.x;
    const int b  = bh >> 4;
    const int h  = bh & 15;
    const int q0 = blockIdx.y * ABR;

    for (int i = tid; i < ABR * 64; i += 256) {
        int r = i >> 6, d = i & 63;
        Qs[r][d] = Q[((size_t)(b * SS + q0 + r) * HH + h) * HD + d];
    }

    float m[4], l[4], a0[4], a1[4];
    #pragma unroll
    for (int i = 0; i < 4; i++) { m[i] = -1e30f; l[i] = 0.f; a0[i] = 0.f; a1[i] = 0.f; }

    int c0 = (q0 > WIN - 1) ? ((q0 - (WIN - 1)) & ~(ABC - 1)) : 0;
    for (int c = c0; c <= q0; c += ABC) {
        __syncthreads();
        for (int i = tid; i < ABC * 64; i += 256) {
            int r = i >> 6, d = i & 63;
            size_t g = ((size_t)(b * SS + c + r) * HH + h) * HD + d;
            Ks[r][d] = K[g];
            Vs[r][d] = V[g];
        }
        __syncthreads();

        #pragma unroll
        for (int ri = 0; ri < 4; ri++) {
            int r = warp * 4 + ri;
            int qpos = q0 + r;
            float s0 = 0.f, s1 = 0.f;
            #pragma unroll
            for (int d = 0; d < 64; d++) {
                float qd = Qs[r][d];
                s0 = fmaf(qd, Ks[lane][d],      s0);
                s1 = fmaf(qd, Ks[lane + 32][d], s1);
            }
            s0 *= 0.125f; s1 *= 0.125f;     // 1/sqrt(64)
            int df0 = qpos - (c + lane);
            int df1 = qpos - (c + lane + 32);
            if (!(df0 >= 0 && df0 < WIN)) s0 = -1e9f;
            if (!(df1 >= 0 && df1 < WIN)) s1 = -1e9f;

            float mx = fmaxf(s0, s1);
            #pragma unroll
            for (int o = 16; o; o >>= 1) mx = fmaxf(mx, __shfl_xor_sync(0xffffffffu, mx, o));
            float mnew = fmaxf(m[ri], mx);
            float scale = expf(m[ri] - mnew);
            m[ri] = mnew;

            float p0 = __expf(s0 - mnew);
            float p1 = __expf(s1 - mnew);
            float ls = p0 + p1;
            #pragma unroll
            for (int o = 16; o; o >>= 1) ls += __shfl_xor_sync(0xffffffffu, ls, o);
            l[ri] = l[ri] * scale + ls;
            a0[ri] *= scale; a1[ri] *= scale;

            Ps[warp][lane] = p0; Ps[warp][lane + 32] = p1;
            __syncwarp();
            #pragma unroll
            for (int j = 0; j < 64; j++) {
                float pj = Ps[warp][j];
                a0[ri] = fmaf(pj, Vs[j][lane],      a0[ri]);
                a1[ri] = fmaf(pj, Vs[j][lane + 32], a1[ri]);
            }
            __syncwarp();
        }
    }

    #pragma unroll
    for (int ri = 0; ri < 4; ri++) {
        int r = warp * 4 + ri;
        size_t g = ((size_t)(b * SS + q0 + r) * HH + h) * HD;
        float invl = 1.0f / l[ri];
        O[g + lane]      = a0[ri] * invl;
        O[g + lane + 32] = a1[ri] * invl;
    }
}

// ---------------- copy ----------------
__global__ void copy_k(const float* __restrict__ src, float* __restrict__ dst)
{
    int i = blockIdx.x * blockDim.x + threadIdx.x;   // MT*DD/4 float4s
    ((float4*)dst)[i] = ((const float4*)src)[i];
}

// ---------------- host orchestration ----------------
extern "C" void kernel_launch(void* const* d_in, const int* in_sizes, int n_in,
                              void* d_out, int out_size)
{
    const float* latents = (const float*)d_in[0];
    const float* cosT    = (const float*)d_in[1];
    const float* sinT    = (const float*)d_in[2];
    const float* wq      = (const float*)d_in[3];
    const float* wk      = (const float*)d_in[4];
    const float* wv      = (const float*)d_in[5];
    const float* wo      = (const float*)d_in[6];
    const float* w1      = (const float*)d_in[7];
    const float* w2      = (const float*)d_in[8];
    const float* wdelta  = (const float*)d_in[9];
    float* out = (float*)d_out;

    float *x, *h, *q, *k, *v, *o, *m1;
    cudaGetSymbolAddress((void**)&x,  g_x);
    cudaGetSymbolAddress((void**)&h,  g_h);
    cudaGetSymbolAddress((void**)&q,  g_q);
    cudaGetSymbolAddress((void**)&k,  g_k);
    cudaGetSymbolAddress((void**)&v,  g_v);
    cudaGetSymbolAddress((void**)&o,  g_o);
    cudaGetSymbolAddress((void**)&m1, g_m1);

    const dim3 gN(DD / GBN, MT / GBM);     // (8, 64)  N=1024
    const dim3 gW(D4 / GBN, MT / GBM);     // (32, 64) N=4096
    const dim3 gA(BB * HH, SS / ABR);      // (64, 64)

    copy_k<<<(MT * DD / 4) / 256, 256>>>(latents, x);

    for (int li = 0; li < LL; li++) {
        const float* wqi = wq + (size_t)li * DD * DD;
        const float* wki = wk + (size_t)li * DD * DD;
        const float* wvi = wv + (size_t)li * DD * DD;
        const float* woi = wo + (size_t)li * DD * DD;
        const float* w1i = w1 + (size_t)li * DD * D4;
        const float* w2i = w2 + (size_t)li * D4 * DD;

        rmsnorm_k<<<MT, 256>>>(x, h);
        gemm_k<EPI_NONE, false><<<gN, 256>>>(h, wqi, nullptr, q, DD, DD);
        gemm_k<EPI_NONE, false><<<gN, 256>>>(h, wki, nullptr, k, DD, DD);
        gemm_k<EPI_NONE, false><<<gN, 256>>>(h, wvi, nullptr, v, DD, DD);
        rope_k<<<(BB * SS * HH * 32) / 256, 256>>>(q, cosT, sinT);
        rope_k<<<(BB * SS * HH * 32) / 256, 256>>>(k, cosT, sinT);
        attn_k<<<gA, 256>>>(q, k, v, o);
        gemm_k<EPI_RESID, false><<<gN, 256>>>(o, woi, x, x, DD, DD);
        rmsnorm_k<<<MT, 256>>>(x, h);
        gemm_k<EPI_SILU, false><<<gW, 256>>>(h, w1i, nullptr, m1, D4, DD);
        gemm_k<EPI_RESID, false><<<gN, 256>>>(m1, w2i, x, x, DD, D4);
    }

    rmsnorm_k<<<MT, 256>>>(x, h);
    gemm_k<EPI_TANH, true><<<gN, 256>>>(h, wdelta, nullptr, out, DD, DD);
}

// round 5
// speedup vs baseline: 1.4452x; 1.4452x over previous
#include <cuda_runtime.h>
#include <cuda_bf16.h>
#include <cstdint>
#include <cstddef>

// ---------------- Problem constants ----------------
#define BB 4
#define SS 2048
#define DD 1024
#define HH 16
#define HD 64
#define LL 4
#define WIN 256
#define MT (BB*SS)          // 8192 rows
#define D4 (4*DD)           // 4096

// ---------------- Scratch (device globals; no allocation) ----------------
__device__ float g_x [MT*DD];
__device__ float g_h [MT*DD];
__device__ float g_q [MT*DD];
__device__ float g_k [MT*DD];
__device__ float g_v [MT*DD];
__device__ float g_o [MT*DD];
__device__ float g_m1[MT*D4];

// bf16 split buffers: activations (max 8192x4096) and all weights (transposed)
#define MEL ((size_t)DD*DD)                 // 1M elems
#define AW_ELEMS ((size_t)MT*D4)            // 32M elems
#define W_ELEMS  (49*MEL)
__device__ __nv_bfloat16 g_ahi[AW_ELEMS];
__device__ __nv_bfloat16 g_alo[AW_ELEMS];
__device__ __nv_bfloat16 g_whi[W_ELEMS];
__device__ __nv_bfloat16 g_wlo[W_ELEMS];

// weight region offsets (elements)
#define OQ  ((size_t)0)
#define OKk (4*MEL)
#define OV  (8*MEL)
#define OO  (12*MEL)
#define O1  (16*MEL)
#define O2  (32*MEL)
#define ODl (48*MEL)

// ---------------- small helpers ----------------
__device__ __forceinline__ uint32_t smem_u32(const void* p){
    uint32_t a;
    asm("{ .reg .u64 t; cvta.to.shared.u64 t, %1; cvt.u32.u64 %0, t; }"
        : "=r"(a) : "l"(p));
    return a;
}
__device__ __forceinline__ void cpa16(uint32_t s, const void* g){
    asm volatile("cp.async.cg.shared.global [%0], [%1], 16;" :: "r"(s), "l"(g));
}
__device__ __forceinline__ void ldsm4(uint32_t* d, uint32_t a){
    asm volatile("ldmatrix.sync.aligned.m8n8.x4.shared.b16 {%0,%1,%2,%3}, [%4];"
        : "=r"(d[0]), "=r"(d[1]), "=r"(d[2]), "=r"(d[3]) : "r"(a));
}
__device__ __forceinline__ void mma16816(float* c, const uint32_t* a, const uint32_t* b){
    asm volatile("mma.sync.aligned.m16n8k16.row.col.f32.bf16.bf16.f32 "
        "{%0,%1,%2,%3}, {%4,%5,%6,%7}, {%8,%9}, {%0,%1,%2,%3};"
        : "+f"(c[0]), "+f"(c[1]), "+f"(c[2]), "+f"(c[3])
        : "r"(a[0]), "r"(a[1]), "r"(a[2]), "r"(a[3]), "r"(b[0]), "r"(b[1]));
}

// ---------------- HMMA split-bf16 GEMM ----------------
// C[M,N] = epi( fp32(A) @ fp32(B)^T ) ; A=[M,K] hi/lo bf16 row-major,
// B=[N,K] hi/lo bf16 row-major (weights pre-transposed).
#define BM 128
#define BN 64
#define BK 32
#define ATILE (BM*64)                 // 8192 bytes (rows of 32 bf16 = 64B)
#define BTILE (BN*64)                 // 4096 bytes
#define STAGE (2*ATILE + 2*BTILE)     // 24576: [Ahi][Alo][Bhi][Blo]
#define SMEMB (2*STAGE)               // 49152

// byte offset of (row r, 16B-chunk c) inside a tile, XOR-swizzled
__device__ __forceinline__ uint32_t swz(int r, int c){
    return (uint32_t)(r * 64 + ((c ^ ((r >> 1) & 3)) << 4));
}

enum { EPI_NONE = 0, EPI_SILU = 1, EPI_RESID = 2, EPI_TANH = 3 };

template<int EPI>
__global__ __launch_bounds__(256, 2)
void hgemm_k(const __nv_bfloat16* __restrict__ Ahi, const __nv_bfloat16* __restrict__ Alo,
             const __nv_bfloat16* __restrict__ Bhi, const __nv_bfloat16* __restrict__ Blo,
             const float* __restrict__ R, float* __restrict__ C, int N, int K)
{
    extern __shared__ char sm[];
    const uint32_t sb = smem_u32(sm);
    const int tid  = threadIdx.x;
    const int warp = tid >> 5;
    const int lane = tid & 31;
    const int m0 = blockIdx.y * BM;
    const int n0 = blockIdx.x * BN;
    const int wm = warp >> 1;            // 0..3  -> m offset wm*32
    const int wn = warp & 1;             // 0..1  -> n offset wn*32

    // ---- async tile loader ----
    auto issue = [&](int st, int kc) {
        uint32_t base = sb + st * STAGE;
        #pragma unroll
        for (int it = 0; it < 2; it++) {           // A: 512 16B-chunks
            int i = tid + it * 256;
            int r = i >> 2, c = i & 3;
            uint32_t so = base + swz(r, c);
            size_t g = (size_t)(m0 + r) * K + kc + c * 8;
            cpa16(so,          Ahi + g);
            cpa16(so + ATILE,  Alo + g);
        }
        {                                          // B: 256 16B-chunks
            int r = tid >> 2, c = tid & 3;
            uint32_t so = base + 2 * ATILE + swz(r, c);
            size_t g = (size_t)(n0 + r) * K + kc + c * 8;
            cpa16(so,          Bhi + g);
            cpa16(so + BTILE,  Blo + g);
        }
        asm volatile("cp.async.commit_group;");
    };

    float acc[2][4][4];
    #pragma unroll
    for (int i = 0; i < 2; i++)
        #pragma unroll
        for (int j = 0; j < 4; j++)
            #pragma unroll
            for (int e = 0; e < 4; e++) acc[i][j][e] = 0.f;

    const int nk = K / BK;
    issue(0, 0);
    for (int i = 0; i < nk; i++) {
        if (i + 1 < nk) {
            issue((i + 1) & 1, (i + 1) * BK);
            asm volatile("cp.async.wait_group 1;");
        } else {
            asm volatile("cp.async.wait_group 0;");
        }
        __syncthreads();

        uint32_t base = sb + (i & 1) * STAGE;
        #pragma unroll
        for (int kk = 0; kk < 2; kk++) {           // two k16 sub-steps
            uint32_t ah[2][4], al[2][4], bh[4][2], bl[4][2];
            #pragma unroll
            for (int mi = 0; mi < 2; mi++) {
                int r = wm * 32 + mi * 16 + (lane & 15);
                int c = kk * 2 + (lane >> 4);
                uint32_t ad = base + swz(r, c);
                ldsm4(ah[mi], ad);
                ldsm4(al[mi], ad + ATILE);
            }
            #pragma unroll
            for (int np = 0; np < 2; np++) {       // each x4 covers n16 x k16
                int r = wn * 32 + np * 16 + (lane & 7) + ((lane >> 4) & 1) * 8;
                int c = kk * 2 + ((lane >> 3) & 1);
                uint32_t bd = base + 2 * ATILE + swz(r, c);
                uint32_t t[4];
                ldsm4(t, bd);
                bh[np*2][0] = t[0]; bh[np*2][1] = t[1];
                bh[np*2+1][0] = t[2]; bh[np*2+1][1] = t[3];
                ldsm4(t, bd + BTILE);
                bl[np*2][0] = t[0]; bl[np*2][1] = t[1];
                bl[np*2+1][0] = t[2]; bl[np*2+1][1] = t[3];
            }
            #pragma unroll
            for (int mi = 0; mi < 2; mi++)
                #pragma unroll
                for (int ni = 0; ni < 4; ni++) {
                    mma16816(acc[mi][ni], ah[mi], bh[ni]);
                    mma16816(acc[mi][ni], ah[mi], bl[ni]);
                    mma16816(acc[mi][ni], al[mi], bh[ni]);
                }
        }
        __syncthreads();
    }

    // ---- epilogue: direct stores (float2 granules) ----
    #pragma unroll
    for (int mi = 0; mi < 2; mi++) {
        #pragma unroll
        for (int ni = 0; ni < 4; ni++) {
            int row = m0 + wm * 32 + mi * 16 + (lane >> 2);
            int col = n0 + wn * 32 + ni * 8 + (lane & 3) * 2;
            float v[4] = { acc[mi][ni][0], acc[mi][ni][1], acc[mi][ni][2], acc[mi][ni][3] };
            size_t o0 = (size_t)row * N + col;
            size_t o1 = (size_t)(row + 8) * N + col;
            if (EPI == EPI_SILU) {
                #pragma unroll
                for (int e = 0; e < 4; e++) v[e] = v[e] / (1.0f + __expf(-v[e]));
            } else if (EPI == EPI_RESID) {
                float2 r0 = *(const float2*)(R + o0);
                float2 r1 = *(const float2*)(R + o1);
                v[0] += r0.x; v[1] += r0.y; v[2] += r1.x; v[3] += r1.y;
            } else if (EPI == EPI_TANH) {
                #pragma unroll
                for (int e = 0; e < 4; e++) v[e] = tanhf(v[e]);
            }
            *(float2*)(C + o0) = make_float2(v[0], v[1]);
            *(float2*)(C + o1) = make_float2(v[2], v[3]);
        }
    }
}

// ---------------- fp32 -> bf16 hi/lo split (same layout) ----------------
__global__ __launch_bounds__(256) void split_k(const float* __restrict__ x,
                                               __nv_bfloat16* __restrict__ hi,
                                               __nv_bfloat16* __restrict__ lo)
{
    size_t i = (size_t)blockIdx.x * 256 + threadIdx.x;
    float4 v = ((const float4*)x)[i];
    __nv_bfloat16 h0 = __float2bfloat16(v.x);
    __nv_bfloat16 h1 = __float2bfloat16(v.y);
    __nv_bfloat16 h2 = __float2bfloat16(v.z);
    __nv_bfloat16 h3 = __float2bfloat16(v.w);
    ((__nv_bfloat162*)hi)[i*2]   = __halves2bfloat162(h0, h1);
    ((__nv_bfloat162*)hi)[i*2+1] = __halves2bfloat162(h2, h3);
    __nv_bfloat16 l0 = __float2bfloat16(v.x - __bfloat162float(h0));
    __nv_bfloat16 l1 = __float2bfloat16(v.y - __bfloat162float(h1));
    __nv_bfloat16 l2 = __float2bfloat16(v.z - __bfloat162float(h2));
    __nv_bfloat16 l3 = __float2bfloat16(v.w - __bfloat162float(h3));
    ((__nv_bfloat162*)lo)[i*2]   = __halves2bfloat162(l0, l1);
    ((__nv_bfloat162*)lo)[i*2+1] = __halves2bfloat162(l2, l3);
}

// ---------------- fp32 W[K,N] -> transposed bf16 hi/lo WT[N,K] ----------------
__global__ __launch_bounds__(256) void splitT_k(const float* __restrict__ src,
                                                __nv_bfloat16* __restrict__ hi,
                                                __nv_bfloat16* __restrict__ lo,
                                                int K, int N)
{
    __shared__ float t[32][33];
    size_t zoff = (size_t)blockIdx.z * (size_t)K * N;
    src += zoff; hi += zoff; lo += zoff;
    int n0 = blockIdx.x * 32, k0 = blockIdx.y * 32;
    int tx = threadIdx.x & 31, ty = threadIdx.x >> 5;   // 32x8
    #pragma unroll
    for (int i = ty; i < 32; i += 8)
        t[i][tx] = src[(size_t)(k0 + i) * N + n0 + tx];
    __syncthreads();
    #pragma unroll
    for (int i = ty; i < 32; i += 8) {
        float v = t[tx][i];
        __nv_bfloat16 h = __float2bfloat16(v);
        size_t o = (size_t)(n0 + i) * K + k0 + tx;
        hi[o] = h;
        lo[o] = __float2bfloat16(v - __bfloat162float(h));
    }
}

// ---------------- RMSNorm (row-wise over D=1024) ----------------
__global__ __launch_bounds__(256) void rmsnorm_k(const float* __restrict__ X,
                                                 float* __restrict__ H)
{
    __shared__ float red[8];
    const int row = blockIdx.x;
    const int tid = threadIdx.x;
    const float4* x4 = (const float4*)(X + (size_t)row * DD);
    float4 v = x4[tid];
    float s = v.x * v.x + v.y * v.y + v.z * v.z + v.w * v.w;
    #pragma unroll
    for (int o = 16; o; o >>= 1) s += __shfl_xor_sync(0xffffffffu, s, o);
    if ((tid & 31) == 0) red[tid >> 5] = s;
    __syncthreads();
    float tot = red[0] + red[1] + red[2] + red[3] + red[4] + red[5] + red[6] + red[7];
    float inv = rsqrtf(tot * (1.0f / DD) + 1e-6f);
    float4 o;
    o.x = v.x * inv; o.y = v.y * inv; o.z = v.z * inv; o.w = v.w * inv;
    ((float4*)(H + (size_t)row * DD))[tid] = o;
}

// ---------------- RoPE (in-place, pair-safe) ----------------
__global__ __launch_bounds__(256) void rope_k(float* __restrict__ Q,
                                              const float* __restrict__ CO,
                                              const float* __restrict__ SI)
{
    int idx = blockIdx.x * blockDim.x + threadIdx.x;
    int d    = idx & 31;
    int rest = idx >> 5;
    int h    = rest & 15;
    int s    = (rest >> 4) & (SS - 1);
    int b    = rest >> 15;
    size_t base = ((size_t)(b * SS + s) * HH + h) * HD;
    float x1 = Q[base + d];
    float x2 = Q[base + d + 32];
    float c1 = CO[s * HD + d],      s1 = SI[s * HD + d];
    float c2 = CO[s * HD + d + 32], s2 = SI[s * HD + d + 32];
    Q[base + d]      = x1 * c1 - x2 * s1;
    Q[base + d + 32] = x2 * c2 + x1 * s2;
}

// ---------------- Sliding-window attention (flash-style) ----------------
#define ABR 32
#define ABC 64

__global__ __launch_bounds__(256) void attn_k(const float* __restrict__ Q,
                                              const float* __restrict__ K,
                                              const float* __restrict__ V,
                                              float* __restrict__ O)
{
    __shared__ float Qs[ABR][64];
    __shared__ float Ks[ABC][65];
    __shared__ float Vs[ABC][64];
    __shared__ float Ps[8][64];

    const int tid  = threadIdx.x;
    const int warp = tid >> 5;
    const int lane = tid & 31;
    const int bh = blockIdx.x;
    const int b  = bh >> 4;
    const int h  = bh & 15;
    const int q0 = blockIdx.y * ABR;

    for (int i = tid; i < ABR * 64; i += 256) {
        int r = i >> 6, d = i & 63;
        Qs[r][d] = Q[((size_t)(b * SS + q0 + r) * HH + h) * HD + d];
    }

    float m[4], l[4], a0[4], a1[4];
    #pragma unroll
    for (int i = 0; i < 4; i++) { m[i] = -1e30f; l[i] = 0.f; a0[i] = 0.f; a1[i] = 0.f; }

    int c0 = (q0 > WIN - 1) ? ((q0 - (WIN - 1)) & ~(ABC - 1)) : 0;
    for (int c = c0; c <= q0; c += ABC) {
        __syncthreads();
        for (int i = tid; i < ABC * 64; i += 256) {
            int r = i >> 6, d = i & 63;
            size_t g = ((size_t)(b * SS + c + r) * HH + h) * HD + d;
            Ks[r][d] = K[g];
            Vs[r][d] = V[g];
        }
        __syncthreads();

        #pragma unroll
        for (int ri = 0; ri < 4; ri++) {
            int r = warp * 4 + ri;
            int qpos = q0 + r;
            float s0 = 0.f, s1 = 0.f;
            #pragma unroll
            for (int d = 0; d < 64; d++) {
                float qd = Qs[r][d];
                s0 = fmaf(qd, Ks[lane][d],      s0);
                s1 = fmaf(qd, Ks[lane + 32][d], s1);
            }
            s0 *= 0.125f; s1 *= 0.125f;
            int df0 = qpos - (c + lane);
            int df1 = qpos - (c + lane + 32);
            if (!(df0 >= 0 && df0 < WIN)) s0 = -1e9f;
            if (!(df1 >= 0 && df1 < WIN)) s1 = -1e9f;

            float mx = fmaxf(s0, s1);
            #pragma unroll
            for (int o = 16; o; o >>= 1) mx = fmaxf(mx, __shfl_xor_sync(0xffffffffu, mx, o));
            float mnew = fmaxf(m[ri], mx);
            float scale = expf(m[ri] - mnew);
            m[ri] = mnew;

            float p0 = __expf(s0 - mnew);
            float p1 = __expf(s1 - mnew);
            float ls = p0 + p1;
            #pragma unroll
            for (int o = 16; o; o >>= 1) ls += __shfl_xor_sync(0xffffffffu, ls, o);
            l[ri] = l[ri] * scale + ls;
            a0[ri] *= scale; a1[ri] *= scale;

            Ps[warp][lane] = p0; Ps[warp][lane + 32] = p1;
            __syncwarp();
            #pragma unroll
            for (int j = 0; j < 64; j++) {
                float pj = Ps[warp][j];
                a0[ri] = fmaf(pj, Vs[j][lane],      a0[ri]);
                a1[ri] = fmaf(pj, Vs[j][lane + 32], a1[ri]);
            }
            __syncwarp();
        }
    }

    #pragma unroll
    for (int ri = 0; ri < 4; ri++) {
        int r = warp * 4 + ri;
        size_t g = ((size_t)(b * SS + q0 + r) * HH + h) * HD;
        float invl = 1.0f / l[ri];
        O[g + lane]      = a0[ri] * invl;
        O[g + lane + 32] = a1[ri] * invl;
    }
}

// ---------------- copy ----------------
__global__ void copy_k(const float* __restrict__ src, float* __restrict__ dst)
{
    int i = blockIdx.x * blockDim.x + threadIdx.x;
    ((float4*)dst)[i] = ((const float4*)src)[i];
}

// ---------------- host orchestration ----------------
extern "C" void kernel_launch(void* const* d_in, const int* in_sizes, int n_in,
                              void* d_out, int out_size)
{
    const float* latents = (const float*)d_in[0];
    const float* cosT    = (const float*)d_in[1];
    const float* sinT    = (const float*)d_in[2];
    const float* wq      = (const float*)d_in[3];
    const float* wk      = (const float*)d_in[4];
    const float* wv      = (const float*)d_in[5];
    const float* wo      = (const float*)d_in[6];
    const float* w1      = (const float*)d_in[7];
    const float* w2      = (const float*)d_in[8];
    const float* wdelta  = (const float*)d_in[9];
    float* out = (float*)d_out;

    float *x, *h, *q, *k, *v, *o, *m1;
    __nv_bfloat16 *ahi, *alo, *whi, *wlo;
    cudaGetSymbolAddress((void**)&x,   g_x);
    cudaGetSymbolAddress((void**)&h,   g_h);
    cudaGetSymbolAddress((void**)&q,   g_q);
    cudaGetSymbolAddress((void**)&k,   g_k);
    cudaGetSymbolAddress((void**)&v,   g_v);
    cudaGetSymbolAddress((void**)&o,   g_o);
    cudaGetSymbolAddress((void**)&m1,  g_m1);
    cudaGetSymbolAddress((void**)&ahi, g_ahi);
    cudaGetSymbolAddress((void**)&alo, g_alo);
    cudaGetSymbolAddress((void**)&whi, g_whi);
    cudaGetSymbolAddress((void**)&wlo, g_wlo);

    cudaFuncSetAttribute(hgemm_k<EPI_NONE>,  cudaFuncAttributeMaxDynamicSharedMemorySize, SMEMB);
    cudaFuncSetAttribute(hgemm_k<EPI_SILU>,  cudaFuncAttributeMaxDynamicSharedMemorySize, SMEMB);
    cudaFuncSetAttribute(hgemm_k<EPI_RESID>, cudaFuncAttributeMaxDynamicSharedMemorySize, SMEMB);
    cudaFuncSetAttribute(hgemm_k<EPI_TANH>,  cudaFuncAttributeMaxDynamicSharedMemorySize, SMEMB);

    const dim3 tb(256);
    // ---- weight conversion (transpose to [N,K], split hi/lo) ----
    splitT_k<<<dim3(DD/32, DD/32, LL), tb>>>(wq, whi + OQ,  wlo + OQ,  DD, DD);
    splitT_k<<<dim3(DD/32, DD/32, LL), tb>>>(wk, whi + OKk, wlo + OKk, DD, DD);
    splitT_k<<<dim3(DD/32, DD/32, LL), tb>>>(wv, whi + OV,  wlo + OV,  DD, DD);
    splitT_k<<<dim3(DD/32, DD/32, LL), tb>>>(wo, whi + OO,  wlo + OO,  DD, DD);
    splitT_k<<<dim3(D4/32, DD/32, LL), tb>>>(w1, whi + O1,  wlo + O1,  DD, D4);
    splitT_k<<<dim3(DD/32, D4/32, LL), tb>>>(w2, whi + O2,  wlo + O2,  D4, DD);
    split_k<<<(int)(MEL/4/256), tb>>>(wdelta, whi + ODl, wlo + ODl);   // already [N,K]

    const dim3 gN(DD / BN, MT / BM);      // (16, 64)
    const dim3 gW(D4 / BN, MT / BM);      // (64, 64)
    const dim3 gA(BB * HH, SS / ABR);

    copy_k<<<(MT * DD / 4) / 256, 256>>>(latents, x);

    for (int li = 0; li < LL; li++) {
        const __nv_bfloat16* bqh = whi + OQ  + (size_t)li * MEL;
        const __nv_bfloat16* bql = wlo + OQ  + (size_t)li * MEL;
        const __nv_bfloat16* bkh = whi + OKk + (size_t)li * MEL;
        const __nv_bfloat16* bkl = wlo + OKk + (size_t)li * MEL;
        const __nv_bfloat16* bvh = whi + OV  + (size_t)li * MEL;
        const __nv_bfloat16* bvl = wlo + OV  + (size_t)li * MEL;
        const __nv_bfloat16* boh = whi + OO  + (size_t)li * MEL;
        const __nv_bfloat16* bol = wlo + OO  + (size_t)li * MEL;
        const __nv_bfloat16* b1h = whi + O1  + (size_t)li * 4 * MEL;
        const __nv_bfloat16* b1l = wlo + O1  + (size_t)li * 4 * MEL;
        const __nv_bfloat16* b2h = whi + O2  + (size_t)li * 4 * MEL;
        const __nv_bfloat16* b2l = wlo + O2  + (size_t)li * 4 * MEL;

        rmsnorm_k<<<MT, 256>>>(x, h);
        split_k<<<MT * DD / 1024, tb>>>(h, ahi, alo);
        hgemm_k<EPI_NONE><<<gN, tb, SMEMB>>>(ahi, alo, bqh, bql, nullptr, q, DD, DD);
        hgemm_k<EPI_NONE><<<gN, tb, SMEMB>>>(ahi, alo, bkh, bkl, nullptr, k, DD, DD);
        hgemm_k<EPI_NONE><<<gN, tb, SMEMB>>>(ahi, alo, bvh, bvl, nullptr, v, DD, DD);
        rope_k<<<(BB * SS * HH * 32) / 256, 256>>>(q, cosT, sinT);
        rope_k<<<(BB * SS * HH * 32) / 256, 256>>>(k, cosT, sinT);
        attn_k<<<gA, 256>>>(q, k, v, o);
        split_k<<<MT * DD / 1024, tb>>>(o, ahi, alo);
        hgemm_k<EPI_RESID><<<gN, tb, SMEMB>>>(ahi, alo, boh, bol, x, x, DD, DD);
        rmsnorm_k<<<MT, 256>>>(x, h);
        split_k<<<MT * DD / 1024, tb>>>(h, ahi, alo);
        hgemm_k<EPI_SILU><<<gW, tb, SMEMB>>>(ahi, alo, b1h, b1l, nullptr, m1, D4, DD);
        split_k<<<MT * D4 / 1024, tb>>>(m1, ahi, alo);
        hgemm_k<EPI_RESID><<<gN, tb, SMEMB>>>(ahi, alo, b2h, b2l, x, x, DD, D4);
    }

    rmsnorm_k<<<MT, 256>>>(x, h);
    split_k<<<MT * DD / 1024, tb>>>(h, ahi, alo);
    hgemm_k<EPI_TANH><<<gN, tb, SMEMB>>>(ahi, alo, whi + ODl, wlo + ODl, nullptr, out, DD, DD);
}

// round 6
// speedup vs baseline: 2.3094x; 1.5980x over previous
#include <cuda_runtime.h>
#include <cuda_bf16.h>
#include <cstdint>
#include <cstddef>

// ---------------- Problem constants ----------------
#define BB 4
#define SS 2048
#define DD 1024
#define HH 16
#define HD 64
#define LL 4
#define WIN 256
#define MT (BB*SS)          // 8192 rows
#define D4 (4*DD)           // 4096

// ---------------- Scratch (device globals; no allocation) ----------------
__device__ float g_x [MT*DD];
__device__ float g_q [MT*DD];
__device__ float g_k [MT*DD];
__device__ float g_v [MT*DD];

#define MEL ((size_t)DD*DD)                 // 1M elems
#define AW2 ((size_t)MT*(DD+D4))            // act split: [0,MT*DD) = D-wide, [MT*DD,..) = 4D-wide
#define W_ELEMS  (49*MEL)
__device__ __nv_bfloat16 g_ahi[AW2];
__device__ __nv_bfloat16 g_alo[AW2];
__device__ __nv_bfloat16 g_whi[W_ELEMS];
__device__ __nv_bfloat16 g_wlo[W_ELEMS];

// weight region offsets (elements)
#define OQ  ((size_t)0)
#define OKk (4*MEL)
#define OV  (8*MEL)
#define OO  (12*MEL)
#define O1  (16*MEL)
#define O2  (32*MEL)
#define ODl (48*MEL)

// ---------------- small helpers ----------------
__device__ __forceinline__ uint32_t smem_u32(const void* p){
    uint32_t a;
    asm("{ .reg .u64 t; cvta.to.shared.u64 t, %1; cvt.u32.u64 %0, t; }"
        : "=r"(a) : "l"(p));
    return a;
}
__device__ __forceinline__ void cpa16(uint32_t s, const void* g){
    asm volatile("cp.async.cg.shared.global [%0], [%1], 16;" :: "r"(s), "l"(g));
}
__device__ __forceinline__ void ldsm4(uint32_t* d, uint32_t a){
    asm volatile("ldmatrix.sync.aligned.m8n8.x4.shared.b16 {%0,%1,%2,%3}, [%4];"
        : "=r"(d[0]), "=r"(d[1]), "=r"(d[2]), "=r"(d[3]) : "r"(a));
}
__device__ __forceinline__ void mma16816(float* c, const uint32_t* a, const uint32_t* b){
    asm volatile("mma.sync.aligned.m16n8k16.row.col.f32.bf16.bf16.f32 "
        "{%0,%1,%2,%3}, {%4,%5,%6,%7}, {%8,%9}, {%0,%1,%2,%3};"
        : "+f"(c[0]), "+f"(c[1]), "+f"(c[2]), "+f"(c[3])
        : "r"(a[0]), "r"(a[1]), "r"(a[2]), "r"(a[3]), "r"(b[0]), "r"(b[1]));
}

// ---------------- HMMA split-bf16 GEMM ----------------
// C[M,N] = epi( fp32(A) @ fp32(B)^T ) ; A=[M,K] hi/lo bf16 row-major,
// B=[N,K] hi/lo bf16 row-major (weights pre-transposed).
// CTA tile 128x128, BK=32, 8 warps = 4(m) x 2(n), warp tile 32x64.
#define BM 128
#define BN 128
#define BK 32
#define ATILE (BM*64)                 // 8192 B  (rows of 32 bf16 = 64B)
#define BTILE (BN*64)                 // 8192 B
#define STAGE (2*ATILE + 2*BTILE)     // 32768: [Ahi][Alo][Bhi][Blo]
#define SMEMB (2*STAGE)               // 65536

// byte offset of (row r, 16B-chunk c) inside a tile, XOR-swizzled
__device__ __forceinline__ uint32_t swz(int r, int c){
    return (uint32_t)(r * 64 + ((c ^ ((r >> 1) & 3)) << 4));
}

enum { EPI_NONE = 0, EPI_SILU_SPLIT = 1, EPI_RESID = 2, EPI_TANH = 3, EPI_ROPE = 4 };

template<int EPI>
__global__ __launch_bounds__(256, 2)
void hgemm_k(const __nv_bfloat16* __restrict__ Ahi, const __nv_bfloat16* __restrict__ Alo,
             const __nv_bfloat16* __restrict__ Bhi, const __nv_bfloat16* __restrict__ Blo,
             const float* __restrict__ R, float* __restrict__ C,
             __nv_bfloat16* __restrict__ Hh, __nv_bfloat16* __restrict__ Hl,
             const float* __restrict__ CO, const float* __restrict__ SI,
             int N, int K)
{
    extern __shared__ char sm[];
    const uint32_t sb = smem_u32(sm);
    const int tid  = threadIdx.x;
    const int warp = tid >> 5;
    const int lane = tid & 31;
    const int m0 = blockIdx.y * BM;
    const int n0 = blockIdx.x * BN;
    const int wm = warp >> 1;            // 0..3  -> m offset wm*32
    const int wn = warp & 1;             // 0..1  -> n offset wn*64

    // ---- async tile loader ----
    auto issue = [&](int st, int kc) {
        uint32_t base = sb + st * STAGE;
        #pragma unroll
        for (int it = 0; it < 2; it++) {           // A: 512 16B-chunks (hi), same lo
            int i = tid + it * 256;
            int r = i >> 2, c = i & 3;
            uint32_t so = base + swz(r, c);
            size_t g = (size_t)(m0 + r) * K + kc + c * 8;
            cpa16(so,          Ahi + g);
            cpa16(so + ATILE,  Alo + g);
        }
        #pragma unroll
        for (int it = 0; it < 2; it++) {           // B: 512 16B-chunks (hi), same lo
            int i = tid + it * 256;
            int r = i >> 2, c = i & 3;
            uint32_t so = base + 2 * ATILE + swz(r, c);
            size_t g = (size_t)(n0 + r) * K + kc + c * 8;
            cpa16(so,          Bhi + g);
            cpa16(so + BTILE,  Blo + g);
        }
        asm volatile("cp.async.commit_group;");
    };

    float acc[2][8][4];
    #pragma unroll
    for (int i = 0; i < 2; i++)
        #pragma unroll
        for (int j = 0; j < 8; j++)
            #pragma unroll
            for (int e = 0; e < 4; e++) acc[i][j][e] = 0.f;

    const int nk = K / BK;
    issue(0, 0);
    for (int i = 0; i < nk; i++) {
        if (i + 1 < nk) {
            issue((i + 1) & 1, (i + 1) * BK);
            asm volatile("cp.async.wait_group 1;");
        } else {
            asm volatile("cp.async.wait_group 0;");
        }
        __syncthreads();

        uint32_t base = sb + (i & 1) * STAGE;
        #pragma unroll
        for (int kk = 0; kk < 2; kk++) {           // two k16 sub-steps
            uint32_t ah[2][4], al[2][4];
            #pragma unroll
            for (int mi = 0; mi < 2; mi++) {
                int r = wm * 32 + mi * 16 + (lane & 15);
                int c = kk * 2 + (lane >> 4);
                uint32_t ad = base + swz(r, c);
                ldsm4(ah[mi], ad);
                ldsm4(al[mi], ad + ATILE);
            }
            #pragma unroll
            for (int np = 0; np < 4; np++) {       // four n16 chunks of the 64-wide warp tile
                int r = wn * 64 + np * 16 + (lane & 7) + ((lane >> 4) & 1) * 8;
                int c = kk * 2 + ((lane >> 3) & 1);
                uint32_t bd = base + 2 * ATILE + swz(r, c);
                uint32_t th[4], tl[4];
                ldsm4(th, bd);
                ldsm4(tl, bd + BTILE);
                #pragma unroll
                for (int mi = 0; mi < 2; mi++) {
                    mma16816(acc[mi][np*2],   ah[mi], th);
                    mma16816(acc[mi][np*2],   ah[mi], tl);
                    mma16816(acc[mi][np*2],   al[mi], th);
                    mma16816(acc[mi][np*2+1], ah[mi], th + 2);
                    mma16816(acc[mi][np*2+1], ah[mi], tl + 2);
                    mma16816(acc[mi][np*2+1], al[mi], th + 2);
                }
            }
        }
        __syncthreads();
    }

    // ---- epilogue ----
    if (EPI == EPI_ROPE) {
        // N==DD; warp n-range (64) == one head. ni and ni+4 hold d and d+32.
        #pragma unroll
        for (int mi = 0; mi < 2; mi++) {
            int row = m0 + wm * 32 + mi * 16 + (lane >> 2);
            int s0 = row & (SS - 1);
            int s1 = s0 + 8;
            #pragma unroll
            for (int np = 0; np < 4; np++) {
                int d = np * 8 + (lane & 3) * 2;       // 0..31
                float2 cA0 = *(const float2*)(CO + s0 * HD + d);
                float2 sA0 = *(const float2*)(SI + s0 * HD + d);
                float2 cB0 = *(const float2*)(CO + s0 * HD + d + 32);
                float2 sB0 = *(const float2*)(SI + s0 * HD + d + 32);
                float2 cA1 = *(const float2*)(CO + s1 * HD + d);
                float2 sA1 = *(const float2*)(SI + s1 * HD + d);
                float2 cB1 = *(const float2*)(CO + s1 * HD + d + 32);
                float2 sB1 = *(const float2*)(SI + s1 * HD + d + 32);
                float* x1 = acc[mi][np];
                float* x2 = acc[mi][np + 4];
                float o1[4], o2[4];
                o1[0] = x1[0] * cA0.x - x2[0] * sA0.x;
                o1[1] = x1[1] * cA0.y - x2[1] * sA0.y;
                o1[2] = x1[2] * cA1.x - x2[2] * sA1.x;
                o1[3] = x1[3] * cA1.y - x2[3] * sA1.y;
                o2[0] = x2[0] * cB0.x + x1[0] * sB0.x;
                o2[1] = x2[1] * cB0.y + x1[1] * sB0.y;
                o2[2] = x2[2] * cB1.x + x1[2] * sB1.x;
                o2[3] = x2[3] * cB1.y + x1[3] * sB1.y;
                int col = n0 + wn * 64 + d;
                size_t g0 = (size_t)row * N + col;
                size_t g1 = (size_t)(row + 8) * N + col;
                *(float2*)(C + g0)      = make_float2(o1[0], o1[1]);
                *(float2*)(C + g1)      = make_float2(o1[2], o1[3]);
                *(float2*)(C + g0 + 32) = make_float2(o2[0], o2[1]);
                *(float2*)(C + g1 + 32) = make_float2(o2[2], o2[3]);
            }
        }
    } else {
        #pragma unroll
        for (int mi = 0; mi < 2; mi++) {
            #pragma unroll
            for (int ni = 0; ni < 8; ni++) {
                int row = m0 + wm * 32 + mi * 16 + (lane >> 2);
                int col = n0 + wn * 64 + ni * 8 + (lane & 3) * 2;
                float v[4] = { acc[mi][ni][0], acc[mi][ni][1], acc[mi][ni][2], acc[mi][ni][3] };
                size_t o0 = (size_t)row * N + col;
                size_t o1 = (size_t)(row + 8) * N + col;
                if (EPI == EPI_SILU_SPLIT) {
                    #pragma unroll
                    for (int e = 0; e < 4; e++) v[e] = v[e] / (1.0f + __expf(-v[e]));
                    __nv_bfloat16 h0 = __float2bfloat16(v[0]);
                    __nv_bfloat16 h1 = __float2bfloat16(v[1]);
                    __nv_bfloat16 h2 = __float2bfloat16(v[2]);
                    __nv_bfloat16 h3 = __float2bfloat16(v[3]);
                    *(__nv_bfloat162*)(Hh + o0) = __halves2bfloat162(h0, h1);
                    *(__nv_bfloat162*)(Hh + o1) = __halves2bfloat162(h2, h3);
                    *(__nv_bfloat162*)(Hl + o0) = __halves2bfloat162(
                        __float2bfloat16(v[0] - __bfloat162float(h0)),
                        __float2bfloat16(v[1] - __bfloat162float(h1)));
                    *(__nv_bfloat162*)(Hl + o1) = __halves2bfloat162(
                        __float2bfloat16(v[2] - __bfloat162float(h2)),
                        __float2bfloat16(v[3] - __bfloat162float(h3)));
                } else {
                    if (EPI == EPI_RESID) {
                        float2 r0 = *(const float2*)(R + o0);
                        float2 r1 = *(const float2*)(R + o1);
                        v[0] += r0.x; v[1] += r0.y; v[2] += r1.x; v[3] += r1.y;
                    } else if (EPI == EPI_TANH) {
                        #pragma unroll
                        for (int e = 0; e < 4; e++) v[e] = tanhf(v[e]);
                    }
                    *(float2*)(C + o0) = make_float2(v[0], v[1]);
                    *(float2*)(C + o1) = make_float2(v[2], v[3]);
                }
            }
        }
    }
}

// ---------------- fp32 -> bf16 hi/lo split (flat) ----------------
__global__ __launch_bounds__(256) void split_k(const float* __restrict__ x,
                                               __nv_bfloat16* __restrict__ hi,
                                               __nv_bfloat16* __restrict__ lo)
{
    size_t i = (size_t)blockIdx.x * 256 + threadIdx.x;
    float4 v = ((const float4*)x)[i];
    __nv_bfloat16 h0 = __float2bfloat16(v.x);
    __nv_bfloat16 h1 = __float2bfloat16(v.y);
    __nv_bfloat16 h2 = __float2bfloat16(v.z);
    __nv_bfloat16 h3 = __float2bfloat16(v.w);
    ((__nv_bfloat162*)hi)[i*2]   = __halves2bfloat162(h0, h1);
    ((__nv_bfloat162*)hi)[i*2+1] = __halves2bfloat162(h2, h3);
    ((__nv_bfloat162*)lo)[i*2]   = __halves2bfloat162(
        __float2bfloat16(v.x - __bfloat162float(h0)),
        __float2bfloat16(v.y - __bfloat162float(h1)));
    ((__nv_bfloat162*)lo)[i*2+1] = __halves2bfloat162(
        __float2bfloat16(v.z - __bfloat162float(h2)),
        __float2bfloat16(v.w - __bfloat162float(h3)));
}

// ---------------- fp32 W[K,N] -> transposed bf16 hi/lo WT[N,K] ----------------
__global__ __launch_bounds__(256) void splitT_k(const float* __restrict__ src,
                                                __nv_bfloat16* __restrict__ hi,
                                                __nv_bfloat16* __restrict__ lo,
                                                int K, int N)
{
    __shared__ float t[32][33];
    size_t zoff = (size_t)blockIdx.z * (size_t)K * N;
    src += zoff; hi += zoff; lo += zoff;
    int n0 = blockIdx.x * 32, k0 = blockIdx.y * 32;
    int tx = threadIdx.x & 31, ty = threadIdx.x >> 5;   // 32x8
    #pragma unroll
    for (int i = ty; i < 32; i += 8)
        t[i][tx] = src[(size_t)(k0 + i) * N + n0 + tx];
    __syncthreads();
    #pragma unroll
    for (int i = ty; i < 32; i += 8) {
        float v = t[tx][i];
        __nv_bfloat16 h = __float2bfloat16(v);
        size_t o = (size_t)(n0 + i) * K + k0 + tx;
        hi[o] = h;
        lo[o] = __float2bfloat16(v - __bfloat162float(h));
    }
}

// ---------------- RMSNorm fused with bf16 split ----------------
__global__ __launch_bounds__(256) void rmsns_k(const float* __restrict__ X,
                                               __nv_bfloat16* __restrict__ Hh,
                                               __nv_bfloat16* __restrict__ Hl)
{
    __shared__ float red[8];
    const int row = blockIdx.x;
    const int tid = threadIdx.x;
    const float4* x4 = (const float4*)(X + (size_t)row * DD);
    float4 v = x4[tid];
    float s = v.x * v.x + v.y * v.y + v.z * v.z + v.w * v.w;
    #pragma unroll
    for (int o = 16; o; o >>= 1) s += __shfl_xor_sync(0xffffffffu, s, o);
    if ((tid & 31) == 0) red[tid >> 5] = s;
    __syncthreads();
    float tot = red[0] + red[1] + red[2] + red[3] + red[4] + red[5] + red[6] + red[7];
    float inv = rsqrtf(tot * (1.0f / DD) + 1e-6f);
    float o0 = v.x * inv, o1 = v.y * inv, o2 = v.z * inv, o3 = v.w * inv;
    __nv_bfloat16 h0 = __float2bfloat16(o0);
    __nv_bfloat16 h1 = __float2bfloat16(o1);
    __nv_bfloat16 h2 = __float2bfloat16(o2);
    __nv_bfloat16 h3 = __float2bfloat16(o3);
    size_t base = (size_t)row * (DD / 2) + tid * 2;
    ((__nv_bfloat162*)Hh)[base]     = __halves2bfloat162(h0, h1);
    ((__nv_bfloat162*)Hh)[base + 1] = __halves2bfloat162(h2, h3);
    ((__nv_bfloat162*)Hl)[base]     = __halves2bfloat162(
        __float2bfloat16(o0 - __bfloat162float(h0)),
        __float2bfloat16(o1 - __bfloat162float(h1)));
    ((__nv_bfloat162*)Hl)[base + 1] = __halves2bfloat162(
        __float2bfloat16(o2 - __bfloat162float(h2)),
        __float2bfloat16(o3 - __bfloat162float(h3)));
}

// ---------------- Sliding-window attention (flash-style, split-bf16 out) ----------------
#define ABR 32
#define ABC 64

__global__ __launch_bounds__(256) void attn_k(const float* __restrict__ Q,
                                              const float* __restrict__ K,
                                              const float* __restrict__ V,
                                              __nv_bfloat16* __restrict__ Oh,
                                              __nv_bfloat16* __restrict__ Ol)
{
    __shared__ float Qs[ABR][64];
    __shared__ float Ks[ABC][65];
    __shared__ float Vs[ABC][64];
    __shared__ float Ps[8][64];

    const int tid  = threadIdx.x;
    const int warp = tid >> 5;
    const int lane = tid & 31;
    const int bh = blockIdx.x;
    const int b  = bh >> 4;
    const int h  = bh & 15;
    const int q0 = blockIdx.y * ABR;

    for (int i = tid; i < ABR * 64; i += 256) {
        int r = i >> 6, d = i & 63;
        Qs[r][d] = Q[((size_t)(b * SS + q0 + r) * HH + h) * HD + d];
    }

    float m[4], l[4], a0[4], a1[4];
    #pragma unroll
    for (int i = 0; i < 4; i++) { m[i] = -1e30f; l[i] = 0.f; a0[i] = 0.f; a1[i] = 0.f; }

    int c0 = (q0 > WIN - 1) ? ((q0 - (WIN - 1)) & ~(ABC - 1)) : 0;
    for (int c = c0; c <= q0; c += ABC) {
        __syncthreads();
        for (int i = tid; i < ABC * 64; i += 256) {
            int r = i >> 6, d = i & 63;
            size_t g = ((size_t)(b * SS + c + r) * HH + h) * HD + d;
            Ks[r][d] = K[g];
            Vs[r][d] = V[g];
        }
        __syncthreads();

        #pragma unroll
        for (int ri = 0; ri < 4; ri++) {
            int r = warp * 4 + ri;
            int qpos = q0 + r;
            float s0 = 0.f, s1 = 0.f;
            #pragma unroll
            for (int d = 0; d < 64; d++) {
                float qd = Qs[r][d];
                s0 = fmaf(qd, Ks[lane][d],      s0);
                s1 = fmaf(qd, Ks[lane + 32][d], s1);
            }
            s0 *= 0.125f; s1 *= 0.125f;
            int df0 = qpos - (c + lane);
            int df1 = qpos - (c + lane + 32);
            if (!(df0 >= 0 && df0 < WIN)) s0 = -1e9f;
            if (!(df1 >= 0 && df1 < WIN)) s1 = -1e9f;

            float mx = fmaxf(s0, s1);
            #pragma unroll
            for (int o = 16; o; o >>= 1) mx = fmaxf(mx, __shfl_xor_sync(0xffffffffu, mx, o));
            float mnew = fmaxf(m[ri], mx);
            float scale = expf(m[ri] - mnew);
            m[ri] = mnew;

            float p0 = __expf(s0 - mnew);
            float p1 = __expf(s1 - mnew);
            float ls = p0 + p1;
            #pragma unroll
            for (int o = 16; o; o >>= 1) ls += __shfl_xor_sync(0xffffffffu, ls, o);
            l[ri] = l[ri] * scale + ls;
            a0[ri] *= scale; a1[ri] *= scale;

            Ps[warp][lane] = p0; Ps[warp][lane + 32] = p1;
            __syncwarp();
            #pragma unroll
            for (int j = 0; j < 64; j++) {
                float pj = Ps[warp][j];
                a0[ri] = fmaf(pj, Vs[j][lane],      a0[ri]);
                a1[ri] = fmaf(pj, Vs[j][lane + 32], a1[ri]);
            }
            __syncwarp();
        }
    }

    #pragma unroll
    for (int ri = 0; ri < 4; ri++) {
        int r = warp * 4 + ri;
        size_t g = ((size_t)(b * SS + q0 + r) * HH + h) * HD;
        float invl = 1.0f / l[ri];
        float v0 = a0[ri] * invl;
        float v1 = a1[ri] * invl;
        __nv_bfloat16 h0 = __float2bfloat16(v0);
        __nv_bfloat16 h1 = __float2bfloat16(v1);
        Oh[g + lane]      = h0;
        Oh[g + lane + 32] = h1;
        Ol[g + lane]      = __float2bfloat16(v0 - __bfloat162float(h0));
        Ol[g + lane + 32] = __float2bfloat16(v1 - __bfloat162float(h1));
    }
}

// ---------------- copy ----------------
__global__ void copy_k(const float* __restrict__ src, float* __restrict__ dst)
{
    int i = blockIdx.x * blockDim.x + threadIdx.x;
    ((float4*)dst)[i] = ((const float4*)src)[i];
}

// ---------------- host orchestration ----------------
extern "C" void kernel_launch(void* const* d_in, const int* in_sizes, int n_in,
                              void* d_out, int out_size)
{
    const float* latents = (const float*)d_in[0];
    const float* cosT    = (const float*)d_in[1];
    const float* sinT    = (const float*)d_in[2];
    const float* wq      = (const float*)d_in[3];
    const float* wk      = (const float*)d_in[4];
    const float* wv      = (const float*)d_in[5];
    const float* wo      = (const float*)d_in[6];
    const float* w1      = (const float*)d_in[7];
    const float* w2      = (const float*)d_in[8];
    const float* wdelta  = (const float*)d_in[9];
    float* out = (float*)d_out;

    float *x, *q, *k, *v;
    __nv_bfloat16 *ahi, *alo, *whi, *wlo;
    cudaGetSymbolAddress((void**)&x,   g_x);
    cudaGetSymbolAddress((void**)&q,   g_q);
    cudaGetSymbolAddress((void**)&k,   g_k);
    cudaGetSymbolAddress((void**)&v,   g_v);
    cudaGetSymbolAddress((void**)&ahi, g_ahi);
    cudaGetSymbolAddress((void**)&alo, g_alo);
    cudaGetSymbolAddress((void**)&whi, g_whi);
    cudaGetSymbolAddress((void**)&wlo, g_wlo);

    __nv_bfloat16* ahi2 = ahi + (size_t)MT * DD;   // 4D-wide split region
    __nv_bfloat16* alo2 = alo + (size_t)MT * DD;

    cudaFuncSetAttribute(hgemm_k<EPI_NONE>,       cudaFuncAttributeMaxDynamicSharedMemorySize, SMEMB);
    cudaFuncSetAttribute(hgemm_k<EPI_SILU_SPLIT>, cudaFuncAttributeMaxDynamicSharedMemorySize, SMEMB);
    cudaFuncSetAttribute(hgemm_k<EPI_RESID>,      cudaFuncAttributeMaxDynamicSharedMemorySize, SMEMB);
    cudaFuncSetAttribute(hgemm_k<EPI_TANH>,       cudaFuncAttributeMaxDynamicSharedMemorySize, SMEMB);
    cudaFuncSetAttribute(hgemm_k<EPI_ROPE>,       cudaFuncAttributeMaxDynamicSharedMemorySize, SMEMB);

    const dim3 tb(256);
    // ---- weight conversion (transpose to [N,K], split hi/lo) ----
    splitT_k<<<dim3(DD/32, DD/32, LL), tb>>>(wq, whi + OQ,  wlo + OQ,  DD, DD);
    splitT_k<<<dim3(DD/32, DD/32, LL), tb>>>(wk, whi + OKk, wlo + OKk, DD, DD);
    splitT_k<<<dim3(DD/32, DD/32, LL), tb>>>(wv, whi + OV,  wlo + OV,  DD, DD);
    splitT_k<<<dim3(DD/32, DD/32, LL), tb>>>(wo, whi + OO,  wlo + OO,  DD, DD);
    splitT_k<<<dim3(D4/32, DD/32, LL), tb>>>(w1, whi + O1,  wlo + O1,  DD, D4);
    splitT_k<<<dim3(DD/32, D4/32, LL), tb>>>(w2, whi + O2,  wlo + O2,  D4, DD);
    split_k<<<(int)(MEL/4/256), tb>>>(wdelta, whi + ODl, wlo + ODl);   // already [N,K]

    const dim3 gN(DD / BN, MT / BM);      // (8, 64)
    const dim3 gW(D4 / BN, MT / BM);      // (32, 64)
    const dim3 gA(BB * HH, SS / ABR);

    copy_k<<<(MT * DD / 4) / 256, 256>>>(latents, x);

    for (int li = 0; li < LL; li++) {
        const __nv_bfloat16* bqh = whi + OQ  + (size_t)li * MEL;
        const __nv_bfloat16* bql = wlo + OQ  + (size_t)li * MEL;
        const __nv_bfloat16* bkh = whi + OKk + (size_t)li * MEL;
        const __nv_bfloat16* bkl = wlo + OKk + (size_t)li * MEL;
        const __nv_bfloat16* bvh = whi + OV  + (size_t)li * MEL;
        const __nv_bfloat16* bvl = wlo + OV  + (size_t)li * MEL;
        const __nv_bfloat16* boh = whi + OO  + (size_t)li * MEL;
        const __nv_bfloat16* bol = wlo + OO  + (size_t)li * MEL;
        const __nv_bfloat16* b1h = whi + O1  + (size_t)li * 4 * MEL;
        const __nv_bfloat16* b1l = wlo + O1  + (size_t)li * 4 * MEL;
        const __nv_bfloat16* b2h = whi + O2  + (size_t)li * 4 * MEL;
        const __nv_bfloat16* b2l = wlo + O2  + (size_t)li * 4 * MEL;

        rmsns_k<<<MT, tb>>>(x, ahi, alo);
        hgemm_k<EPI_ROPE><<<gN, tb, SMEMB>>>(ahi, alo, bqh, bql, nullptr, q, nullptr, nullptr, cosT, sinT, DD, DD);
        hgemm_k<EPI_ROPE><<<gN, tb, SMEMB>>>(ahi, alo, bkh, bkl, nullptr, k, nullptr, nullptr, cosT, sinT, DD, DD);
        hgemm_k<EPI_NONE><<<gN, tb, SMEMB>>>(ahi, alo, bvh, bvl, nullptr, v, nullptr, nullptr, nullptr, nullptr, DD, DD);
        attn_k<<<gA, tb>>>(q, k, v, ahi, alo);
        hgemm_k<EPI_RESID><<<gN, tb, SMEMB>>>(ahi, alo, boh, bol, x, x, nullptr, nullptr, nullptr, nullptr, DD, DD);
        rmsns_k<<<MT, tb>>>(x, ahi, alo);
        hgemm_k<EPI_SILU_SPLIT><<<gW, tb, SMEMB>>>(ahi, alo, b1h, b1l, nullptr, nullptr, ahi2, alo2, nullptr, nullptr, D4, DD);
        hgemm_k<EPI_RESID><<<gN, tb, SMEMB>>>(ahi2, alo2, b2h, b2l, x, x, nullptr, nullptr, nullptr, nullptr, DD, D4);
    }

    rmsns_k<<<MT, tb>>>(x, ahi, alo);
    hgemm_k<EPI_TANH><<<gN, tb, SMEMB>>>(ahi, alo, whi + ODl, wlo + ODl, nullptr, out, nullptr, nullptr, nullptr, nullptr, DD, DD);
}

// round 8
// speedup vs baseline: 2.4130x; 1.0449x over previous
#include <cuda_runtime.h>
#include <cuda_bf16.h>
#include <cstdint>
#include <cstddef>

// ---------------- Problem constants ----------------
#define BB 4
#define SS 2048
#define DD 1024
#define HH 16
#define HD 64
#define LL 4
#define WIN 256
#define MT (BB*SS)          // 8192 rows
#define D4 (4*DD)           // 4096

// ---------------- Scratch (device globals; no allocation) ----------------
__device__ float g_x [MT*DD];
__device__ float g_q [MT*DD];
__device__ float g_k [MT*DD];
__device__ float g_v [MT*DD];

#define MEL ((size_t)DD*DD)                 // 1M elems
#define AW2 ((size_t)MT*(DD+D4))
#define W_ELEMS  (49*MEL)
__device__ __nv_bfloat16 g_ahi[AW2];
__device__ __nv_bfloat16 g_alo[AW2];
__device__ __nv_bfloat16 g_whi[W_ELEMS];
__device__ __nv_bfloat16 g_wlo[W_ELEMS];

// weight region offsets (elements)
// [0,12MEL): per-layer QKV blocks, layer li at li*3MEL = [wq MEL][wk MEL][wv MEL]
#define OQKV ((size_t)0)
#define OO  (12*MEL)
#define O1  (16*MEL)
#define O2  (32*MEL)
#define ODl (48*MEL)

// ---------------- small helpers ----------------
__device__ __forceinline__ uint32_t smem_u32(const void* p){
    uint32_t a;
    asm("{ .reg .u64 t; cvta.to.shared.u64 t, %1; cvt.u32.u64 %0, t; }"
        : "=r"(a) : "l"(p));
    return a;
}
__device__ __forceinline__ void cpa16(uint32_t s, const void* g){
    asm volatile("cp.async.cg.shared.global [%0], [%1], 16;" :: "r"(s), "l"(g));
}
__device__ __forceinline__ void ldsm4(uint32_t* d, uint32_t a){
    asm volatile("ldmatrix.sync.aligned.m8n8.x4.shared.b16 {%0,%1,%2,%3}, [%4];"
        : "=r"(d[0]), "=r"(d[1]), "=r"(d[2]), "=r"(d[3]) : "r"(a));
}
__device__ __forceinline__ void mma16816(float* c, const uint32_t* a, const uint32_t* b){
    asm volatile("mma.sync.aligned.m16n8k16.row.col.f32.bf16.bf16.f32 "
        "{%0,%1,%2,%3}, {%4,%5,%6,%7}, {%8,%9}, {%0,%1,%2,%3};"
        : "+f"(c[0]), "+f"(c[1]), "+f"(c[2]), "+f"(c[3])
        : "r"(a[0]), "r"(a[1]), "r"(a[2]), "r"(a[3]), "r"(b[0]), "r"(b[1]));
}

// ---------------- HMMA split-bf16 GEMM ----------------
// C[M,N] = epi( fp32(A) @ fp32(B)^T ) ; A=[M,K] hi/lo bf16 row-major,
// B=[N,K] hi/lo bf16 row-major (weights pre-transposed).
// CTA tile 128x128, BK=32, 8 warps = 4(m) x 2(n), warp tile 32x64.
// 3-stage cp.async pipeline, ONE __syncthreads per iteration.
#define BM 128
#define BN 128
#define BK 32
#define ATILE (BM*64)                 // 8192 B
#define BTILE (BN*64)                 // 8192 B
#define STAGE (2*ATILE + 2*BTILE)     // 32768
#define NSTG 3
#define SMEMB (NSTG*STAGE)            // 98304

__device__ __forceinline__ uint32_t swz(int r, int c){
    return (uint32_t)(r * 64 + ((c ^ ((r >> 1) & 3)) << 4));
}

enum { EPI_NONE = 0, EPI_SILU_SPLIT = 1, EPI_RESID = 2, EPI_TANH = 3, EPI_QKV = 5 };

template<int EPI>
__global__ __launch_bounds__(256, 2)
void hgemm_k(const __nv_bfloat16* __restrict__ Ahi, const __nv_bfloat16* __restrict__ Alo,
             const __nv_bfloat16* __restrict__ Bhi, const __nv_bfloat16* __restrict__ Blo,
             const float* __restrict__ R, float* __restrict__ C,
             float* __restrict__ C2, float* __restrict__ C3,
             __nv_bfloat16* __restrict__ Hh, __nv_bfloat16* __restrict__ Hl,
             const float* __restrict__ CO, const float* __restrict__ SI,
             int N, int K)
{
    extern __shared__ char sm[];
    const uint32_t sb = smem_u32(sm);
    const int tid  = threadIdx.x;
    const int warp = tid >> 5;
    const int lane = tid & 31;
    const int m0 = blockIdx.y * BM;
    const int n0 = blockIdx.x * BN;
    const int wm = warp >> 1;
    const int wn = warp & 1;

    auto issue = [&](int st, int kc) {
        uint32_t base = sb + st * STAGE;
        #pragma unroll
        for (int it = 0; it < 2; it++) {
            int i = tid + it * 256;
            int r = i >> 2, c = i & 3;
            uint32_t so = base + swz(r, c);
            size_t g = (size_t)(m0 + r) * K + kc + c * 8;
            cpa16(so,          Ahi + g);
            cpa16(so + ATILE,  Alo + g);
        }
        #pragma unroll
        for (int it = 0; it < 2; it++) {
            int i = tid + it * 256;
            int r = i >> 2, c = i & 3;
            uint32_t so = base + 2 * ATILE + swz(r, c);
            size_t g = (size_t)(n0 + r) * K + kc + c * 8;
            cpa16(so,          Bhi + g);
            cpa16(so + BTILE,  Blo + g);
        }
        asm volatile("cp.async.commit_group;");
    };

    float acc[2][8][4];
    #pragma unroll
    for (int i = 0; i < 2; i++)
        #pragma unroll
        for (int j = 0; j < 8; j++)
            #pragma unroll
            for (int e = 0; e < 4; e++) acc[i][j][e] = 0.f;

    const int nk = K / BK;
    issue(0, 0);
    issue(1, BK);
    int stg = 0;                       // stage index of iter i (i % 3)
    for (int i = 0; i < nk; i++) {
        if (i + 1 < nk) { asm volatile("cp.async.wait_group 1;"); }
        else            { asm volatile("cp.async.wait_group 0;"); }
        __syncthreads();
        if (i + 2 < nk) {
            int ns = stg + 2; if (ns >= NSTG) ns -= NSTG;
            issue(ns, (i + 2) * BK);
        }

        uint32_t base = sb + stg * STAGE;
        #pragma unroll
        for (int kk = 0; kk < 2; kk++) {
            uint32_t ah[2][4], al[2][4];
            #pragma unroll
            for (int mi = 0; mi < 2; mi++) {
                int r = wm * 32 + mi * 16 + (lane & 15);
                int c = kk * 2 + (lane >> 4);
                uint32_t ad = base + swz(r, c);
                ldsm4(ah[mi], ad);
                ldsm4(al[mi], ad + ATILE);
            }
            #pragma unroll
            for (int np = 0; np < 4; np++) {
                int r = wn * 64 + np * 16 + (lane & 7) + ((lane >> 4) & 1) * 8;
                int c = kk * 2 + ((lane >> 3) & 1);
                uint32_t bd = base + 2 * ATILE + swz(r, c);
                uint32_t th[4], tl[4];
                ldsm4(th, bd);
                ldsm4(tl, bd + BTILE);
                #pragma unroll
                for (int mi = 0; mi < 2; mi++) {
                    mma16816(acc[mi][np*2],   ah[mi], th);
                    mma16816(acc[mi][np*2],   ah[mi], tl);
                    mma16816(acc[mi][np*2],   al[mi], th);
                    mma16816(acc[mi][np*2+1], ah[mi], th + 2);
                    mma16816(acc[mi][np*2+1], ah[mi], tl + 2);
                    mma16816(acc[mi][np*2+1], al[mi], th + 2);
                }
            }
        }
        if (++stg >= NSTG) stg = 0;
    }

    // ---- epilogue ----
    if (EPI == EPI_QKV) {
        // B rows span [0,3072): seg 0=Q(rope), 1=K(rope), 2=V(plain). BN=128 so
        // the whole CTA is in one segment. Warp n-range (64) == one head.
        int seg = n0 >> 10;
        int nb  = n0 & 1023;
        float* dst = (seg == 0) ? C : ((seg == 1) ? C2 : C3);
        if (seg < 2) {
            #pragma unroll
            for (int mi = 0; mi < 2; mi++) {
                int row = m0 + wm * 32 + mi * 16 + (lane >> 2);
                int s0 = row & (SS - 1);
                int s1 = s0 + 8;
                #pragma unroll
                for (int np = 0; np < 4; np++) {
                    int d = np * 8 + (lane & 3) * 2;       // 0..31
                    float2 cA0 = *(const float2*)(CO + s0 * HD + d);
                    float2 sA0 = *(const float2*)(SI + s0 * HD + d);
                    float2 cB0 = *(const float2*)(CO + s0 * HD + d + 32);
                    float2 sB0 = *(const float2*)(SI + s0 * HD + d + 32);
                    float2 cA1 = *(const float2*)(CO + s1 * HD + d);
                    float2 sA1 = *(const float2*)(SI + s1 * HD + d);
                    float2 cB1 = *(const float2*)(CO + s1 * HD + d + 32);
                    float2 sB1 = *(const float2*)(SI + s1 * HD + d + 32);
                    float* x1 = acc[mi][np];
                    float* x2 = acc[mi][np + 4];
                    float o1[4], o2[4];
                    o1[0] = x1[0] * cA0.x - x2[0] * sA0.x;
                    o1[1] = x1[1] * cA0.y - x2[1] * sA0.y;
                    o1[2] = x1[2] * cA1.x - x2[2] * sA1.x;
                    o1[3] = x1[3] * cA1.y - x2[3] * sA1.y;
                    o2[0] = x2[0] * cB0.x + x1[0] * sB0.x;
                    o2[1] = x2[1] * cB0.y + x1[1] * sB0.y;
                    o2[2] = x2[2] * cB1.x + x1[2] * sB1.x;
                    o2[3] = x2[3] * cB1.y + x1[3] * sB1.y;
                    int col = nb + wn * 64 + d;
                    size_t g0 = (size_t)row * DD + col;
                    size_t g1 = (size_t)(row + 8) * DD + col;
                    *(float2*)(dst + g0)      = make_float2(o1[0], o1[1]);
                    *(float2*)(dst + g1)      = make_float2(o1[2], o1[3]);
                    *(float2*)(dst + g0 + 32) = make_float2(o2[0], o2[1]);
                    *(float2*)(dst + g1 + 32) = make_float2(o2[2], o2[3]);
                }
            }
        } else {
            #pragma unroll
            for (int mi = 0; mi < 2; mi++) {
                #pragma unroll
                for (int ni = 0; ni < 8; ni++) {
                    int row = m0 + wm * 32 + mi * 16 + (lane >> 2);
                    int col = nb + wn * 64 + ni * 8 + (lane & 3) * 2;
                    size_t g0 = (size_t)row * DD + col;
                    size_t g1 = (size_t)(row + 8) * DD + col;
                    *(float2*)(dst + g0) = make_float2(acc[mi][ni][0], acc[mi][ni][1]);
                    *(float2*)(dst + g1) = make_float2(acc[mi][ni][2], acc[mi][ni][3]);
                }
            }
        }
    } else {
        #pragma unroll
        for (int mi = 0; mi < 2; mi++) {
            #pragma unroll
            for (int ni = 0; ni < 8; ni++) {
                int row = m0 + wm * 32 + mi * 16 + (lane >> 2);
                int col = n0 + wn * 64 + ni * 8 + (lane & 3) * 2;
                float v[4] = { acc[mi][ni][0], acc[mi][ni][1], acc[mi][ni][2], acc[mi][ni][3] };
                size_t o0 = (size_t)row * N + col;
                size_t o1 = (size_t)(row + 8) * N + col;
                if (EPI == EPI_SILU_SPLIT) {
                    #pragma unroll
                    for (int e = 0; e < 4; e++) v[e] = v[e] / (1.0f + __expf(-v[e]));
                    __nv_bfloat16 h0 = __float2bfloat16(v[0]);
                    __nv_bfloat16 h1 = __float2bfloat16(v[1]);
                    __nv_bfloat16 h2 = __float2bfloat16(v[2]);
                    __nv_bfloat16 h3 = __float2bfloat16(v[3]);
                    *(__nv_bfloat162*)(Hh + o0) = __halves2bfloat162(h0, h1);
                    *(__nv_bfloat162*)(Hh + o1) = __halves2bfloat162(h2, h3);
                    *(__nv_bfloat162*)(Hl + o0) = __halves2bfloat162(
                        __float2bfloat16(v[0] - __bfloat162float(h0)),
                        __float2bfloat16(v[1] - __bfloat162float(h1)));
                    *(__nv_bfloat162*)(Hl + o1) = __halves2bfloat162(
                        __float2bfloat16(v[2] - __bfloat162float(h2)),
                        __float2bfloat16(v[3] - __bfloat162float(h3)));
                } else {
                    if (EPI == EPI_RESID) {
                        float2 r0 = *(const float2*)(R + o0);
                        float2 r1 = *(const float2*)(R + o1);
                        v[0] += r0.x; v[1] += r0.y; v[2] += r1.x; v[3] += r1.y;
                    } else if (EPI == EPI_TANH) {
                        #pragma unroll
                        for (int e = 0; e < 4; e++) v[e] = tanhf(v[e]);
                    }
                    *(float2*)(C + o0) = make_float2(v[0], v[1]);
                    *(float2*)(C + o1) = make_float2(v[2], v[3]);
                }
            }
        }
    }
}

// ---------------- fp32 -> bf16 hi/lo split (flat) ----------------
__global__ __launch_bounds__(256) void split_k(const float* __restrict__ x,
                                               __nv_bfloat16* __restrict__ hi,
                                               __nv_bfloat16* __restrict__ lo)
{
    size_t i = (size_t)blockIdx.x * 256 + threadIdx.x;
    float4 v = ((const float4*)x)[i];
    __nv_bfloat16 h0 = __float2bfloat16(v.x);
    __nv_bfloat16 h1 = __float2bfloat16(v.y);
    __nv_bfloat16 h2 = __float2bfloat16(v.z);
    __nv_bfloat16 h3 = __float2bfloat16(v.w);
    ((__nv_bfloat162*)hi)[i*2]   = __halves2bfloat162(h0, h1);
    ((__nv_bfloat162*)hi)[i*2+1] = __halves2bfloat162(h2, h3);
    ((__nv_bfloat162*)lo)[i*2]   = __halves2bfloat162(
        __float2bfloat16(v.x - __bfloat162float(h0)),
        __float2bfloat16(v.y - __bfloat162float(h1)));
    ((__nv_bfloat162*)lo)[i*2+1] = __halves2bfloat162(
        __float2bfloat16(v.z - __bfloat162float(h2)),
        __float2bfloat16(v.w - __bfloat162float(h3)));
}

// ---------------- fp32 W[K,N] -> transposed bf16 hi/lo WT[N,K] ----------------
__global__ __launch_bounds__(256) void splitT_k(const float* __restrict__ src,
                                                __nv_bfloat16* __restrict__ hi,
                                                __nv_bfloat16* __restrict__ lo,
                                                int K, int N, size_t dstStride)
{
    __shared__ float t[32][33];
    src += (size_t)blockIdx.z * (size_t)K * N;
    hi  += (size_t)blockIdx.z * dstStride;
    lo  += (size_t)blockIdx.z * dstStride;
    int n0 = blockIdx.x * 32, k0 = blockIdx.y * 32;
    int tx = threadIdx.x & 31, ty = threadIdx.x >> 5;
    #pragma unroll
    for (int i = ty; i < 32; i += 8)
        t[i][tx] = src[(size_t)(k0 + i) * N + n0 + tx];
    __syncthreads();
    #pragma unroll
    for (int i = ty; i < 32; i += 8) {
        float v = t[tx][i];
        __nv_bfloat16 h = __float2bfloat16(v);
        size_t o = (size_t)(n0 + i) * K + k0 + tx;
        hi[o] = h;
        lo[o] = __float2bfloat16(v - __bfloat162float(h));
    }
}

// ---------------- RMSNorm fused with bf16 split ----------------
__global__ __launch_bounds__(256) void rmsns_k(const float* __restrict__ X,
                                               __nv_bfloat16* __restrict__ Hh,
                                               __nv_bfloat16* __restrict__ Hl)
{
    __shared__ float red[8];
    const int row = blockIdx.x;
    const int tid = threadIdx.x;
    const float4* x4 = (const float4*)(X + (size_t)row * DD);
    float4 v = x4[tid];
    float s = v.x * v.x + v.y * v.y + v.z * v.z + v.w * v.w;
    #pragma unroll
    for (int o = 16; o; o >>= 1) s += __shfl_xor_sync(0xffffffffu, s, o);
    if ((tid & 31) == 0) red[tid >> 5] = s;
    __syncthreads();
    float tot = red[0] + red[1] + red[2] + red[3] + red[4] + red[5] + red[6] + red[7];
    float inv = rsqrtf(tot * (1.0f / DD) + 1e-6f);
    float o0 = v.x * inv, o1 = v.y * inv, o2 = v.z * inv, o3 = v.w * inv;
    __nv_bfloat16 h0 = __float2bfloat16(o0);
    __nv_bfloat16 h1 = __float2bfloat16(o1);
    __nv_bfloat16 h2 = __float2bfloat16(o2);
    __nv_bfloat16 h3 = __float2bfloat16(o3);
    size_t base = (size_t)row * (DD / 2) + tid * 2;
    ((__nv_bfloat162*)Hh)[base]     = __halves2bfloat162(h0, h1);
    ((__nv_bfloat162*)Hh)[base + 1] = __halves2bfloat162(h2, h3);
    ((__nv_bfloat162*)Hl)[base]     = __halves2bfloat162(
        __float2bfloat16(o0 - __bfloat162float(h0)),
        __float2bfloat16(o1 - __bfloat162float(h1)));
    ((__nv_bfloat162*)Hl)[base + 1] = __halves2bfloat162(
        __float2bfloat16(o2 - __bfloat162float(h2)),
        __float2bfloat16(o3 - __bfloat162float(h3)));
}

// ---------------- Sliding-window attention (flash-style, split-bf16 out) ----------------
#define ABR 32
#define ABC 64

__global__ __launch_bounds__(256) void attn_k(const float* __restrict__ Q,
                                              const float* __restrict__ K,
                                              const float* __restrict__ V,
                                              __nv_bfloat16* __restrict__ Oh,
                                              __nv_bfloat16* __restrict__ Ol)
{
    __shared__ float Qs[ABR][64];
    __shared__ float Ks[ABC][65];
    __shared__ float Vs[ABC][64];
    __shared__ float Ps[8][64];

    const int tid  = threadIdx.x;
    const int warp = tid >> 5;
    const int lane = tid & 31;
    const int bh = blockIdx.x;
    const int b  = bh >> 4;
    const int h  = bh & 15;
    const int q0 = blockIdx.y * ABR;

    for (int i = tid; i < ABR * 64; i += 256) {
        int r = i >> 6, d = i & 63;
        Qs[r][d] = Q[((size_t)(b * SS + q0 + r) * HH + h) * HD + d];
    }

    float m[4], l[4], a0[4], a1[4];
    #pragma unroll
    for (int i = 0; i < 4; i++) { m[i] = -1e30f; l[i] = 0.f; a0[i] = 0.f; a1[i] = 0.f; }

    int c0 = (q0 > WIN - 1) ? ((q0 - (WIN - 1)) & ~(ABC - 1)) : 0;
    for (int c = c0; c <= q0; c += ABC) {
        __syncthreads();
        for (int i = tid; i < ABC * 64; i += 256) {
            int r = i >> 6, d = i & 63;
            size_t g = ((size_t)(b * SS + c + r) * HH + h) * HD + d;
            Ks[r][d] = K[g];
            Vs[r][d] = V[g];
        }
        __syncthreads();

        #pragma unroll
        for (int ri = 0; ri < 4; ri++) {
            int r = warp * 4 + ri;
            int qpos = q0 + r;
            float s0 = 0.f, s1 = 0.f;
            #pragma unroll
            for (int d = 0; d < 64; d++) {
                float qd = Qs[r][d];
                s0 = fmaf(qd, Ks[lane][d],      s0);
                s1 = fmaf(qd, Ks[lane + 32][d], s1);
            }
            s0 *= 0.125f; s1 *= 0.125f;
            int df0 = qpos - (c + lane);
            int df1 = qpos - (c + lane + 32);
            if (!(df0 >= 0 && df0 < WIN)) s0 = -1e9f;
            if (!(df1 >= 0 && df1 < WIN)) s1 = -1e9f;

            float mx = fmaxf(s0, s1);
            #pragma unroll
            for (int o = 16; o; o >>= 1) mx = fmaxf(mx, __shfl_xor_sync(0xffffffffu, mx, o));
            float mnew = fmaxf(m[ri], mx);
            float scale = expf(m[ri] - mnew);
            m[ri] = mnew;

            float p0 = __expf(s0 - mnew);
            float p1 = __expf(s1 - mnew);
            float ls = p0 + p1;
            #pragma unroll
            for (int o = 16; o; o >>= 1) ls += __shfl_xor_sync(0xffffffffu, ls, o);
            l[ri] = l[ri] * scale + ls;
            a0[ri] *= scale; a1[ri] *= scale;

            Ps[warp][lane] = p0; Ps[warp][lane + 32] = p1;
            __syncwarp();
            #pragma unroll
            for (int j = 0; j < 64; j++) {
                float pj = Ps[warp][j];
                a0[ri] = fmaf(pj, Vs[j][lane],      a0[ri]);
                a1[ri] = fmaf(pj, Vs[j][lane + 32], a1[ri]);
            }
            __syncwarp();
        }
    }

    #pragma unroll
    for (int ri = 0; ri < 4; ri++) {
        int r = warp * 4 + ri;
        size_t g = ((size_t)(b * SS + q0 + r) * HH + h) * HD;
        float invl = 1.0f / l[ri];
        float v0 = a0[ri] * invl;
        float v1 = a1[ri] * invl;
        __nv_bfloat16 h0 = __float2bfloat16(v0);
        __nv_bfloat16 h1 = __float2bfloat16(v1);
        Oh[g + lane]      = h0;
        Oh[g + lane + 32] = h1;
        Ol[g + lane]      = __float2bfloat16(v0 - __bfloat162float(h0));
        Ol[g + lane + 32] = __float2bfloat16(v1 - __bfloat162float(h1));
    }
}

// ---------------- copy ----------------
__global__ void copy_k(const float* __restrict__ src, float* __restrict__ dst)
{
    int i = blockIdx.x * blockDim.x + threadIdx.x;
    ((float4*)dst)[i] = ((const float4*)src)[i];
}

// ---------------- host orchestration ----------------
extern "C" void kernel_launch(void* const* d_in, const int* in_sizes, int n_in,
                              void* d_out, int out_size)
{
    const float* latents = (const float*)d_in[0];
    const float* cosT    = (const float*)d_in[1];
    const float* sinT    = (const float*)d_in[2];
    const float* wq      = (const float*)d_in[3];
    const float* wk      = (const float*)d_in[4];
    const float* wv      = (const float*)d_in[5];
    const float* wo      = (const float*)d_in[6];
    const float* w1      = (const float*)d_in[7];
    const float* w2      = (const float*)d_in[8];
    const float* wdelta  = (const float*)d_in[9];
    float* out = (float*)d_out;

    float *x, *q, *k, *v;
    __nv_bfloat16 *ahi, *alo, *whi, *wlo;
    cudaGetSymbolAddress((void**)&x,   g_x);
    cudaGetSymbolAddress((void**)&q,   g_q);
    cudaGetSymbolAddress((void**)&k,   g_k);
    cudaGetSymbolAddress((void**)&v,   g_v);
    cudaGetSymbolAddress((void**)&ahi, g_ahi);
    cudaGetSymbolAddress((void**)&alo, g_alo);
    cudaGetSymbolAddress((void**)&whi, g_whi);
    cudaGetSymbolAddress((void**)&wlo, g_wlo);

    __nv_bfloat16* ahi2 = ahi + (size_t)MT * DD;
    __nv_bfloat16* alo2 = alo + (size_t)MT * DD;

    cudaFuncSetAttribute(hgemm_k<EPI_QKV>,        cudaFuncAttributeMaxDynamicSharedMemorySize, SMEMB);
    cudaFuncSetAttribute(hgemm_k<EPI_SILU_SPLIT>, cudaFuncAttributeMaxDynamicSharedMemorySize, SMEMB);
    cudaFuncSetAttribute(hgemm_k<EPI_RESID>,      cudaFuncAttributeMaxDynamicSharedMemorySize, SMEMB);
    cudaFuncSetAttribute(hgemm_k<EPI_TANH>,       cudaFuncAttributeMaxDynamicSharedMemorySize, SMEMB);

    const dim3 tb(256);
    // ---- weight conversion: QKV packed per layer, others transposed+split ----
    splitT_k<<<dim3(DD/32, DD/32, LL), tb>>>(wq, whi + OQKV,           wlo + OQKV,           DD, DD, 3*MEL);
    splitT_k<<<dim3(DD/32, DD/32, LL), tb>>>(wk, whi + OQKV + MEL,     wlo + OQKV + MEL,     DD, DD, 3*MEL);
    splitT_k<<<dim3(DD/32, DD/32, LL), tb>>>(wv, whi + OQKV + 2*MEL,   wlo + OQKV + 2*MEL,   DD, DD, 3*MEL);
    splitT_k<<<dim3(DD/32, DD/32, LL), tb>>>(wo, whi + OO,  wlo + OO,  DD, DD, MEL);
    splitT_k<<<dim3(D4/32, DD/32, LL), tb>>>(w1, whi + O1,  wlo + O1,  DD, D4, 4*MEL);
    splitT_k<<<dim3(DD/32, D4/32, LL), tb>>>(w2, whi + O2,  wlo + O2,  D4, DD, 4*MEL);
    split_k<<<(int)(MEL/4/256), tb>>>(wdelta, whi + ODl, wlo + ODl);

    const dim3 gQKV(3 * DD / BN, MT / BM);  // (24, 64)
    const dim3 gN(DD / BN, MT / BM);        // (8, 64)
    const dim3 gW(D4 / BN, MT / BM);        // (32, 64)
    const dim3 gA(BB * HH, SS / ABR);

    copy_k<<<(MT * DD / 4) / 256, 256>>>(latents, x);

    for (int li = 0; li < LL; li++) {
        const __nv_bfloat16* bQh = whi + OQKV + (size_t)li * 3 * MEL;
        const __nv_bfloat16* bQl = wlo + OQKV + (size_t)li * 3 * MEL;
        const __nv_bfloat16* boh = whi + OO  + (size_t)li * MEL;
        const __nv_bfloat16* bol = wlo + OO  + (size_t)li * MEL;
        const __nv_bfloat16* b1h = whi + O1  + (size_t)li * 4 * MEL;
        const __nv_bfloat16* b1l = wlo + O1  + (size_t)li * 4 * MEL;
        const __nv_bfloat16* b2h = whi + O2  + (size_t)li * 4 * MEL;
        const __nv_bfloat16* b2l = wlo + O2  + (size_t)li * 4 * MEL;

        rmsns_k<<<MT, tb>>>(x, ahi, alo);
        hgemm_k<EPI_QKV><<<gQKV, tb, SMEMB>>>(ahi, alo, bQh, bQl, nullptr, q, k, v,
                                              nullptr, nullptr, cosT, sinT, DD, DD);
        attn_k<<<gA, tb>>>(q, k, v, ahi, alo);
        hgemm_k<EPI_RESID><<<gN, tb, SMEMB>>>(ahi, alo, boh, bol, x, x, nullptr, nullptr,
                                              nullptr, nullptr, nullptr, nullptr, DD, DD);
        rmsns_k<<<MT, tb>>>(x, ahi, alo);
        hgemm_k<EPI_SILU_SPLIT><<<gW, tb, SMEMB>>>(ahi, alo, b1h, b1l, nullptr, nullptr, nullptr, nullptr,
                                                   ahi2, alo2, nullptr, nullptr, D4, DD);
        hgemm_k<EPI_RESID><<<gN, tb, SMEMB>>>(ahi2, alo2, b2h, b2l, x, x, nullptr, nullptr,
                                              nullptr, nullptr, nullptr, nullptr, DD, D4);
    }

    rmsns_k<<<MT, tb>>>(x, ahi, alo);
    hgemm_k<EPI_TANH><<<gN, tb, SMEMB>>>(ahi, alo, whi + ODl, wlo + ODl, nullptr, out, nullptr, nullptr,
                                         nullptr, nullptr, nullptr, nullptr, DD, DD);
}

// round 11
// speedup vs baseline: 2.8383x; 1.1762x over previous
#include <cuda_runtime.h>
#include <cuda_bf16.h>
#include <cstdint>
#include <cstddef>

// ---------------- Problem constants ----------------
#define BB 4
#define SS 2048
#define DD 1024
#define HH 16
#define HD 64
#define LL 4
#define WIN 256
#define MT (BB*SS)          // 8192 rows
#define D4 (4*DD)           // 4096

// ---------------- Scratch (device globals; no allocation) ----------------
__device__ float g_x [MT*DD];
__device__ float g_q [MT*DD];
__device__ float g_k [MT*DD];
__device__ float g_v [MT*DD];

#define MEL ((size_t)DD*DD)                 // 1M elems
#define AW2 ((size_t)MT*(DD+D4))
#define W_ELEMS  (49*MEL)
__device__ __nv_bfloat16 g_ahi[AW2];
__device__ __nv_bfloat16 g_alo[AW2];
__device__ __nv_bfloat16 g_whi[W_ELEMS];
__device__ __nv_bfloat16 g_wlo[W_ELEMS];

// weight region offsets (elements)
#define OQKV ((size_t)0)
#define OO  (12*MEL)
#define O1  (16*MEL)
#define O2  (32*MEL)
#define ODl (48*MEL)

// ---------------- small helpers ----------------
__device__ __forceinline__ uint32_t smem_u32(const void* p){
    uint32_t a;
    asm("{ .reg .u64 t; cvta.to.shared.u64 t, %1; cvt.u32.u64 %0, t; }"
        : "=r"(a) : "l"(p));
    return a;
}
__device__ __forceinline__ void cpa16(uint32_t s, const void* g){
    asm volatile("cp.async.cg.shared.global [%0], [%1], 16;" :: "r"(s), "l"(g));
}
__device__ __forceinline__ void ldsm4(uint32_t* d, uint32_t a){
    asm volatile("ldmatrix.sync.aligned.m8n8.x4.shared.b16 {%0,%1,%2,%3}, [%4];"
        : "=r"(d[0]), "=r"(d[1]), "=r"(d[2]), "=r"(d[3]) : "r"(a));
}
__device__ __forceinline__ void mma16816(float* c, const uint32_t* a, const uint32_t* b){
    asm volatile("mma.sync.aligned.m16n8k16.row.col.f32.bf16.bf16.f32 "
        "{%0,%1,%2,%3}, {%4,%5,%6,%7}, {%8,%9}, {%0,%1,%2,%3};"
        : "+f"(c[0]), "+f"(c[1]), "+f"(c[2]), "+f"(c[3])
        : "r"(a[0]), "r"(a[1]), "r"(a[2]), "r"(a[3]), "r"(b[0]), "r"(b[1]));
}

// ---------------- HMMA split-bf16 GEMM ----------------
#define BM 128
#define BN 128
#define BK 32
#define ATILE (BM*64)                 // 8192 B
#define BTILE (BN*64)                 // 8192 B
#define STAGE (2*ATILE + 2*BTILE)     // 32768
#define NSTG 3
#define SMEMB (NSTG*STAGE)            // 98304

__device__ __forceinline__ uint32_t swz(int r, int c){
    return (uint32_t)(r * 64 + ((c ^ ((r >> 1) & 3)) << 4));
}

enum { EPI_NONE = 0, EPI_SILU_SPLIT = 1, EPI_RESID = 2, EPI_TANH = 3, EPI_QKV = 5 };

template<int EPI>
__global__ __launch_bounds__(256, 2)
void hgemm_k(const __nv_bfloat16* __restrict__ Ahi, const __nv_bfloat16* __restrict__ Alo,
             const __nv_bfloat16* __restrict__ Bhi, const __nv_bfloat16* __restrict__ Blo,
             const float* __restrict__ R, float* __restrict__ C,
             float* __restrict__ C2, float* __restrict__ C3,
             __nv_bfloat16* __restrict__ Hh, __nv_bfloat16* __restrict__ Hl,
             const float* __restrict__ CO, const float* __restrict__ SI,
             int N, int K)
{
    extern __shared__ char sm[];
    const uint32_t sb = smem_u32(sm);
    const int tid  = threadIdx.x;
    const int warp = tid >> 5;
    const int lane = tid & 31;
    const int m0 = blockIdx.y * BM;
    const int n0 = blockIdx.x * BN;
    const int wm = warp >> 1;
    const int wn = warp & 1;

    auto issue = [&](int st, int kc) {
        uint32_t base = sb + st * STAGE;
        #pragma unroll
        for (int it = 0; it < 2; it++) {
            int i = tid + it * 256;
            int r = i >> 2, c = i & 3;
            uint32_t so = base + swz(r, c);
            size_t g = (size_t)(m0 + r) * K + kc + c * 8;
            cpa16(so,          Ahi + g);
            cpa16(so + ATILE,  Alo + g);
        }
        #pragma unroll
        for (int it = 0; it < 2; it++) {
            int i = tid + it * 256;
            int r = i >> 2, c = i & 3;
            uint32_t so = base + 2 * ATILE + swz(r, c);
            size_t g = (size_t)(n0 + r) * K + kc + c * 8;
            cpa16(so,          Bhi + g);
            cpa16(so + BTILE,  Blo + g);
        }
        asm volatile("cp.async.commit_group;");
    };

    float acc[2][8][4];
    #pragma unroll
    for (int i = 0; i < 2; i++)
        #pragma unroll
        for (int j = 0; j < 8; j++)
            #pragma unroll
            for (int e = 0; e < 4; e++) acc[i][j][e] = 0.f;

    const int nk = K / BK;
    issue(0, 0);
    issue(1, BK);
    int stg = 0;
    for (int i = 0; i < nk; i++) {
        if (i + 1 < nk) { asm volatile("cp.async.wait_group 1;"); }
        else            { asm volatile("cp.async.wait_group 0;"); }
        __syncthreads();
        if (i + 2 < nk) {
            int ns = stg + 2; if (ns >= NSTG) ns -= NSTG;
            issue(ns, (i + 2) * BK);
        }

        uint32_t base = sb + stg * STAGE;
        #pragma unroll
        for (int kk = 0; kk < 2; kk++) {
            uint32_t ah[2][4], al[2][4];
            #pragma unroll
            for (int mi = 0; mi < 2; mi++) {
                int r = wm * 32 + mi * 16 + (lane & 15);
                int c = kk * 2 + (lane >> 4);
                uint32_t ad = base + swz(r, c);
                ldsm4(ah[mi], ad);
                ldsm4(al[mi], ad + ATILE);
            }
            #pragma unroll
            for (int nh = 0; nh < 2; nh++) {         // np-pairs: {0,1}, {2,3}
                uint32_t th[2][4], tl[2][4];
                #pragma unroll
                for (int p2 = 0; p2 < 2; p2++) {
                    int np = nh * 2 + p2;
                    int r = wn * 64 + np * 16 + (lane & 7) + ((lane >> 4) & 1) * 8;
                    int c = kk * 2 + ((lane >> 3) & 1);
                    uint32_t bd = base + 2 * ATILE + swz(r, c);
                    ldsm4(th[p2], bd);
                    ldsm4(tl[p2], bd + BTILE);
                }
                #pragma unroll
                for (int p2 = 0; p2 < 2; p2++) {
                    int np = nh * 2 + p2;
                    #pragma unroll
                    for (int mi = 0; mi < 2; mi++) {
                        mma16816(acc[mi][np*2],   ah[mi], th[p2]);
                        mma16816(acc[mi][np*2],   ah[mi], tl[p2]);
                        mma16816(acc[mi][np*2],   al[mi], th[p2]);
                        mma16816(acc[mi][np*2+1], ah[mi], th[p2] + 2);
                        mma16816(acc[mi][np*2+1], ah[mi], tl[p2] + 2);
                        mma16816(acc[mi][np*2+1], al[mi], th[p2] + 2);
                    }
                }
            }
        }
        if (++stg >= NSTG) stg = 0;
    }

    // ---- epilogue ----
    if (EPI == EPI_QKV) {
        int seg = n0 >> 10;
        int nb  = n0 & 1023;
        float* dst = (seg == 0) ? C : ((seg == 1) ? C2 : C3);
        if (seg < 2) {
            #pragma unroll
            for (int mi = 0; mi < 2; mi++) {
                int row = m0 + wm * 32 + mi * 16 + (lane >> 2);
                int s0 = row & (SS - 1);
                int s1 = s0 + 8;
                #pragma unroll
                for (int np = 0; np < 4; np++) {
                    int d = np * 8 + (lane & 3) * 2;
                    float2 cA0 = *(const float2*)(CO + s0 * HD + d);
                    float2 sA0 = *(const float2*)(SI + s0 * HD + d);
                    float2 cB0 = *(const float2*)(CO + s0 * HD + d + 32);
                    float2 sB0 = *(const float2*)(SI + s0 * HD + d + 32);
                    float2 cA1 = *(const float2*)(CO + s1 * HD + d);
                    float2 sA1 = *(const float2*)(SI + s1 * HD + d);
                    float2 cB1 = *(const float2*)(CO + s1 * HD + d + 32);
                    float2 sB1 = *(const float2*)(SI + s1 * HD + d + 32);
                    float* x1 = acc[mi][np];
                    float* x2 = acc[mi][np + 4];
                    float o1[4], o2[4];
                    o1[0] = x1[0] * cA0.x - x2[0] * sA0.x;
                    o1[1] = x1[1] * cA0.y - x2[1] * sA0.y;
                    o1[2] = x1[2] * cA1.x - x2[2] * sA1.x;
                    o1[3] = x1[3] * cA1.y - x2[3] * sA1.y;
                    o2[0] = x2[0] * cB0.x + x1[0] * sB0.x;
                    o2[1] = x2[1] * cB0.y + x1[1] * sB0.y;
                    o2[2] = x2[2] * cB1.x + x1[2] * sB1.x;
                    o2[3] = x2[3] * cB1.y + x1[3] * sB1.y;
                    int col = nb + wn * 64 + d;
                    size_t g0 = (size_t)row * DD + col;
                    size_t g1 = (size_t)(row + 8) * DD + col;
                    *(float2*)(dst + g0)      = make_float2(o1[0], o1[1]);
                    *(float2*)(dst + g1)      = make_float2(o1[2], o1[3]);
                    *(float2*)(dst + g0 + 32) = make_float2(o2[0], o2[1]);
                    *(float2*)(dst + g1 + 32) = make_float2(o2[2], o2[3]);
                }
            }
        } else {
            #pragma unroll
            for (int mi = 0; mi < 2; mi++) {
                #pragma unroll
                for (int ni = 0; ni < 8; ni++) {
                    int row = m0 + wm * 32 + mi * 16 + (lane >> 2);
                    int col = nb + wn * 64 + ni * 8 + (lane & 3) * 2;
                    size_t g0 = (size_t)row * DD + col;
                    size_t g1 = (size_t)(row + 8) * DD + col;
                    *(float2*)(dst + g0) = make_float2(acc[mi][ni][0], acc[mi][ni][1]);
                    *(float2*)(dst + g1) = make_float2(acc[mi][ni][2], acc[mi][ni][3]);
                }
            }
        }
    } else {
        #pragma unroll
        for (int mi = 0; mi < 2; mi++) {
            #pragma unroll
            for (int ni = 0; ni < 8; ni++) {
                int row = m0 + wm * 32 + mi * 16 + (lane >> 2);
                int col = n0 + wn * 64 + ni * 8 + (lane & 3) * 2;
                float v[4] = { acc[mi][ni][0], acc[mi][ni][1], acc[mi][ni][2], acc[mi][ni][3] };
                size_t o0 = (size_t)row * N + col;
                size_t o1 = (size_t)(row + 8) * N + col;
                if (EPI == EPI_SILU_SPLIT) {
                    #pragma unroll
                    for (int e = 0; e < 4; e++) v[e] = v[e] / (1.0f + __expf(-v[e]));
                    __nv_bfloat16 h0 = __float2bfloat16(v[0]);
                    __nv_bfloat16 h1 = __float2bfloat16(v[1]);
                    __nv_bfloat16 h2 = __float2bfloat16(v[2]);
                    __nv_bfloat16 h3 = __float2bfloat16(v[3]);
                    *(__nv_bfloat162*)(Hh + o0) = __halves2bfloat162(h0, h1);
                    *(__nv_bfloat162*)(Hh + o1) = __halves2bfloat162(h2, h3);
                    *(__nv_bfloat162*)(Hl + o0) = __halves2bfloat162(
                        __float2bfloat16(v[0] - __bfloat162float(h0)),
                        __float2bfloat16(v[1] - __bfloat162float(h1)));
                    *(__nv_bfloat162*)(Hl + o1) = __halves2bfloat162(
                        __float2bfloat16(v[2] - __bfloat162float(h2)),
                        __float2bfloat16(v[3] - __bfloat162float(h3)));
                } else {
                    if (EPI == EPI_RESID) {
                        float2 r0 = *(const float2*)(R + o0);
                        float2 r1 = *(const float2*)(R + o1);
                        v[0] += r0.x; v[1] += r0.y; v[2] += r1.x; v[3] += r1.y;
                    } else if (EPI == EPI_TANH) {
                        #pragma unroll
                        for (int e = 0; e < 4; e++) v[e] = tanhf(v[e]);
                    }
                    *(float2*)(C + o0) = make_float2(v[0], v[1]);
                    *(float2*)(C + o1) = make_float2(v[2], v[3]);
                }
            }
        }
    }
}

// ---------------- fp32 -> bf16 hi/lo split (flat) ----------------
__global__ __launch_bounds__(256) void split_k(const float* __restrict__ x,
                                               __nv_bfloat16* __restrict__ hi,
                                               __nv_bfloat16* __restrict__ lo)
{
    size_t i = (size_t)blockIdx.x * 256 + threadIdx.x;
    float4 v = ((const float4*)x)[i];
    __nv_bfloat16 h0 = __float2bfloat16(v.x);
    __nv_bfloat16 h1 = __float2bfloat16(v.y);
    __nv_bfloat16 h2 = __float2bfloat16(v.z);
    __nv_bfloat16 h3 = __float2bfloat16(v.w);
    ((__nv_bfloat162*)hi)[i*2]   = __halves2bfloat162(h0, h1);
    ((__nv_bfloat162*)hi)[i*2+1] = __halves2bfloat162(h2, h3);
    ((__nv_bfloat162*)lo)[i*2]   = __halves2bfloat162(
        __float2bfloat16(v.x - __bfloat162float(h0)),
        __float2bfloat16(v.y - __bfloat162float(h1)));
    ((__nv_bfloat162*)lo)[i*2+1] = __halves2bfloat162(
        __float2bfloat16(v.z - __bfloat162float(h2)),
        __float2bfloat16(v.w - __bfloat162float(h3)));
}

// ---------------- fp32 W[K,N] -> transposed bf16 hi/lo WT[N,K] ----------------
__global__ __launch_bounds__(256) void splitT_k(const float* __restrict__ src,
                                                __nv_bfloat16* __restrict__ hi,
                                                __nv_bfloat16* __restrict__ lo,
                                                int K, int N, size_t dstStride)
{
    __shared__ float t[32][33];
    src += (size_t)blockIdx.z * (size_t)K * N;
    hi  += (size_t)blockIdx.z * dstStride;
    lo  += (size_t)blockIdx.z * dstStride;
    int n0 = blockIdx.x * 32, k0 = blockIdx.y * 32;
    int tx = threadIdx.x & 31, ty = threadIdx.x >> 5;
    #pragma unroll
    for (int i = ty; i < 32; i += 8)
        t[i][tx] = src[(size_t)(k0 + i) * N + n0 + tx];
    __syncthreads();
    #pragma unroll
    for (int i = ty; i < 32; i += 8) {
        float v = t[tx][i];
        __nv_bfloat16 h = __float2bfloat16(v);
        size_t o = (size_t)(n0 + i) * K + k0 + tx;
        hi[o] = h;
        lo[o] = __float2bfloat16(v - __bfloat162float(h));
    }
}

// ---------------- RMSNorm fused with bf16 split ----------------
__global__ __launch_bounds__(256) void rmsns_k(const float* __restrict__ X,
                                               __nv_bfloat16* __restrict__ Hh,
                                               __nv_bfloat16* __restrict__ Hl)
{
    __shared__ float red[8];
    const int row = blockIdx.x;
    const int tid = threadIdx.x;
    const float4* x4 = (const float4*)(X + (size_t)row * DD);
    float4 v = x4[tid];
    float s = v.x * v.x + v.y * v.y + v.z * v.z + v.w * v.w;
    #pragma unroll
    for (int o = 16; o; o >>= 1) s += __shfl_xor_sync(0xffffffffu, s, o);
    if ((tid & 31) == 0) red[tid >> 5] = s;
    __syncthreads();
    float tot = red[0] + red[1] + red[2] + red[3] + red[4] + red[5] + red[6] + red[7];
    float inv = rsqrtf(tot * (1.0f / DD) + 1e-6f);
    float o0 = v.x * inv, o1 = v.y * inv, o2 = v.z * inv, o3 = v.w * inv;
    __nv_bfloat16 h0 = __float2bfloat16(o0);
    __nv_bfloat16 h1 = __float2bfloat16(o1);
    __nv_bfloat16 h2 = __float2bfloat16(o2);
    __nv_bfloat16 h3 = __float2bfloat16(o3);
    size_t base = (size_t)row * (DD / 2) + tid * 2;
    ((__nv_bfloat162*)Hh)[base]     = __halves2bfloat162(h0, h1);
    ((__nv_bfloat162*)Hh)[base + 1] = __halves2bfloat162(h2, h3);
    ((__nv_bfloat162*)Hl)[base]     = __halves2bfloat162(
        __float2bfloat16(o0 - __bfloat162float(h0)),
        __float2bfloat16(o1 - __bfloat162float(h1)));
    ((__nv_bfloat162*)Hl)[base + 1] = __halves2bfloat162(
        __float2bfloat16(o2 - __bfloat162float(h2)),
        __float2bfloat16(o3 - __bfloat162float(h3)));
}

// ---------------- Sliding-window attention (flash-style, split-bf16 out) ----------------
// Dynamic smem layout (bytes):
//   Qs [32][64] f32   @ 0        (8192)
//   Ks [64][65] f32   @ 8192     (16640)
//   Vs [64][64] f32   @ 24832    (16384)
//   Ps [8][4][64] f32 @ 41216    (8192)
#define ATT_SMEM 49408
#define ABR 32
#define ABC 64

__global__ __launch_bounds__(256) void attn_k(const float* __restrict__ Q,
                                              const float* __restrict__ K,
                                              const float* __restrict__ V,
                                              __nv_bfloat16* __restrict__ Oh,
                                              __nv_bfloat16* __restrict__ Ol)
{
    extern __shared__ float asm_[];
    float* Qs = asm_;                       // [32][64]
    float* Ks = asm_ + 2048;                // [64][65]
    float* Vs = asm_ + 2048 + 64 * 65;      // [64][64]
    float* Ps = Vs + 4096;                  // [8][4][64]

    const int tid  = threadIdx.x;
    const int warp = tid >> 5;
    const int lane = tid & 31;
    const int bh = blockIdx.x;
    const int b  = bh >> 4;
    const int h  = bh & 15;
    const int q0 = blockIdx.y * ABR;

    for (int i = tid; i < ABR * 64; i += 256) {
        int r = i >> 6, d = i & 63;
        Qs[r * 64 + d] = Q[((size_t)(b * SS + q0 + r) * HH + h) * HD + d];
    }

    float m[4], l[4], a0[4], a1[4];
    #pragma unroll
    for (int i = 0; i < 4; i++) { m[i] = -1e30f; l[i] = 0.f; a0[i] = 0.f; a1[i] = 0.f; }

    int c0 = (q0 > WIN - 1) ? ((q0 - (WIN - 1)) & ~(ABC - 1)) : 0;
    for (int c = c0; c <= q0; c += ABC) {
        __syncthreads();
        for (int i = tid; i < ABC * 64; i += 256) {
            int r = i >> 6, d = i & 63;
            size_t g = ((size_t)(b * SS + c + r) * HH + h) * HD + d;
            Ks[r * 65 + d] = K[g];
            Vs[r * 64 + d] = V[g];
        }
        __syncthreads();

        // ---- scores: d-outer, 4 q-rows inner (Ks reads shared across ri) ----
        float s0[4] = {0.f, 0.f, 0.f, 0.f};
        float s1[4] = {0.f, 0.f, 0.f, 0.f};
        #pragma unroll
        for (int d = 0; d < 64; d++) {
            float k0 = Ks[lane * 65 + d];
            float k1 = Ks[(lane + 32) * 65 + d];
            #pragma unroll
            for (int ri = 0; ri < 4; ri++) {
                float qd = Qs[(warp * 4 + ri) * 64 + d];
                s0[ri] = fmaf(qd, k0, s0[ri]);
                s1[ri] = fmaf(qd, k1, s1[ri]);
            }
        }
        // ---- per-row softmax update ----
        #pragma unroll
        for (int ri = 0; ri < 4; ri++) {
            int qpos = q0 + warp * 4 + ri;
            float t0 = s0[ri] * 0.125f;
            float t1 = s1[ri] * 0.125f;
            int df0 = qpos - (c + lane);
            int df1 = qpos - (c + lane + 32);
            if (!(df0 >= 0 && df0 < WIN)) t0 = -1e9f;
            if (!(df1 >= 0 && df1 < WIN)) t1 = -1e9f;

            float mx = fmaxf(t0, t1);
            #pragma unroll
            for (int o = 16; o; o >>= 1) mx = fmaxf(mx, __shfl_xor_sync(0xffffffffu, mx, o));
            float mnew = fmaxf(m[ri], mx);
            float scale = expf(m[ri] - mnew);
            m[ri] = mnew;

            float p0 = __expf(t0 - mnew);
            float p1 = __expf(t1 - mnew);
            float ls = p0 + p1;
            #pragma unroll
            for (int o = 16; o; o >>= 1) ls += __shfl_xor_sync(0xffffffffu, ls, o);
            l[ri] = l[ri] * scale + ls;
            a0[ri] *= scale; a1[ri] *= scale;

            Ps[(warp * 4 + ri) * 64 + lane]      = p0;
            Ps[(warp * 4 + ri) * 64 + lane + 32] = p1;
        }
        __syncwarp();
        // ---- PV: j-outer, 4 q-rows inner (Vs reads shared across ri) ----
        #pragma unroll
        for (int j = 0; j < 64; j++) {
            float v0 = Vs[j * 64 + lane];
            float v1 = Vs[j * 64 + lane + 32];
            #pragma unroll
            for (int ri = 0; ri < 4; ri++) {
                float pj = Ps[(warp * 4 + ri) * 64 + j];
                a0[ri] = fmaf(pj, v0, a0[ri]);
                a1[ri] = fmaf(pj, v1, a1[ri]);
            }
        }
        __syncwarp();
    }

    #pragma unroll
    for (int ri = 0; ri < 4; ri++) {
        int r = warp * 4 + ri;
        size_t g = ((size_t)(b * SS + q0 + r) * HH + h) * HD;
        float invl = 1.0f / l[ri];
        float v0 = a0[ri] * invl;
        float v1 = a1[ri] * invl;
        __nv_bfloat16 h0 = __float2bfloat16(v0);
        __nv_bfloat16 h1 = __float2bfloat16(v1);
        Oh[g + lane]      = h0;
        Oh[g + lane + 32] = h1;
        Ol[g + lane]      = __float2bfloat16(v0 - __bfloat162float(h0));
        Ol[g + lane + 32] = __float2bfloat16(v1 - __bfloat162float(h1));
    }
}

// ---------------- host orchestration ----------------
extern "C" void kernel_launch(void* const* d_in, const int* in_sizes, int n_in,
                              void* d_out, int out_size)
{
    const float* latents = (const float*)d_in[0];
    const float* cosT    = (const float*)d_in[1];
    const float* sinT    = (const float*)d_in[2];
    const float* wq      = (const float*)d_in[3];
    const float* wk      = (const float*)d_in[4];
    const float* wv      = (const float*)d_in[5];
    const float* wo      = (const float*)d_in[6];
    const float* w1      = (const float*)d_in[7];
    const float* w2      = (const float*)d_in[8];
    const float* wdelta  = (const float*)d_in[9];
    float* out = (float*)d_out;

    float *x, *q, *k, *v;
    __nv_bfloat16 *ahi, *alo, *whi, *wlo;
    cudaGetSymbolAddress((void**)&x,   g_x);
    cudaGetSymbolAddress((void**)&q,   g_q);
    cudaGetSymbolAddress((void**)&k,   g_k);
    cudaGetSymbolAddress((void**)&v,   g_v);
    cudaGetSymbolAddress((void**)&ahi, g_ahi);
    cudaGetSymbolAddress((void**)&alo, g_alo);
    cudaGetSymbolAddress((void**)&whi, g_whi);
    cudaGetSymbolAddress((void**)&wlo, g_wlo);

    __nv_bfloat16* ahi2 = ahi + (size_t)MT * DD;
    __nv_bfloat16* alo2 = alo + (size_t)MT * DD;

    cudaFuncSetAttribute(hgemm_k<EPI_QKV>,        cudaFuncAttributeMaxDynamicSharedMemorySize, SMEMB);
    cudaFuncSetAttribute(hgemm_k<EPI_SILU_SPLIT>, cudaFuncAttributeMaxDynamicSharedMemorySize, SMEMB);
    cudaFuncSetAttribute(hgemm_k<EPI_RESID>,      cudaFuncAttributeMaxDynamicSharedMemorySize, SMEMB);
    cudaFuncSetAttribute(hgemm_k<EPI_TANH>,       cudaFuncAttributeMaxDynamicSharedMemorySize, SMEMB);
    cudaFuncSetAttribute(attn_k,                  cudaFuncAttributeMaxDynamicSharedMemorySize, ATT_SMEM);

    const dim3 tb(256);
    // ---- weight conversion: QKV packed per layer, others transposed+split ----
    splitT_k<<<dim3(DD/32, DD/32, LL), tb>>>(wq, whi + OQKV,         wlo + OQKV,         DD, DD, 3*MEL);
    splitT_k<<<dim3(DD/32, DD/32, LL), tb>>>(wk, whi + OQKV + MEL,   wlo + OQKV + MEL,   DD, DD, 3*MEL);
    splitT_k<<<dim3(DD/32, DD/32, LL), tb>>>(wv, whi + OQKV + 2*MEL, wlo + OQKV + 2*MEL, DD, DD, 3*MEL);
    splitT_k<<<dim3(DD/32, DD/32, LL), tb>>>(wo, whi + OO,  wlo + OO,  DD, DD, MEL);
    splitT_k<<<dim3(D4/32, DD/32, LL), tb>>>(w1, whi + O1,  wlo + O1,  DD, D4, 4*MEL);
    splitT_k<<<dim3(DD/32, D4/32, LL), tb>>>(w2, whi + O2,  wlo + O2,  D4, DD, 4*MEL);
    split_k<<<(int)(MEL/4/256), tb>>>(wdelta, whi + ODl, wlo + ODl);

    const dim3 gQKV(3 * DD / BN, MT / BM);  // (24, 64)
    const dim3 gN(DD / BN, MT / BM);        // (8, 64)
    const dim3 gW(D4 / BN, MT / BM);        // (32, 64)
    const dim3 gA(BB * HH, SS / ABR);

    for (int li = 0; li < LL; li++) {
        const __nv_bfloat16* bQh = whi + OQKV + (size_t)li * 3 * MEL;
        const __nv_bfloat16* bQl = wlo + OQKV + (size_t)li * 3 * MEL;
        const __nv_bfloat16* boh = whi + OO  + (size_t)li * MEL;
        const __nv_bfloat16* bol = wlo + OO  + (size_t)li * MEL;
        const __nv_bfloat16* b1h = whi + O1  + (size_t)li * 4 * MEL;
        const __nv_bfloat16* b1l = wlo + O1  + (size_t)li * 4 * MEL;
        const __nv_bfloat16* b2h = whi + O2  + (size_t)li * 4 * MEL;
        const __nv_bfloat16* b2l = wlo + O2  + (size_t)li * 4 * MEL;

        const float* xin = (li == 0) ? latents : x;   // layer-0 reads latents directly

        rmsns_k<<<MT, tb>>>(xin, ahi, alo);
        hgemm_k<EPI_QKV><<<gQKV, tb, SMEMB>>>(ahi, alo, bQh, bQl, nullptr, q, k, v,
                                              nullptr, nullptr, cosT, sinT, DD, DD);
        attn_k<<<gA, tb, ATT_SMEM>>>(q, k, v, ahi, alo);
        hgemm_k<EPI_RESID><<<gN, tb, SMEMB>>>(ahi, alo, boh, bol, xin, x, nullptr, nullptr,
                                              nullptr, nullptr, nullptr, nullptr, DD, DD);
        rmsns_k<<<MT, tb>>>(x, ahi, alo);
        hgemm_k<EPI_SILU_SPLIT><<<gW, tb, SMEMB>>>(ahi, alo, b1h, b1l, nullptr, nullptr, nullptr, nullptr,
                                                   ahi2, alo2, nullptr, nullptr, D4, DD);
        hgemm_k<EPI_RESID><<<gN, tb, SMEMB>>>(ahi2, alo2, b2h, b2l, x, x, nullptr, nullptr,
                                              nullptr, nullptr, nullptr, nullptr, DD, D4);
    }

    rmsns_k<<<MT, tb>>>(x, ahi, alo);
    hgemm_k<EPI_TANH><<<gN, tb, SMEMB>>>(ahi, alo, whi + ODl, wlo + ODl, nullptr, out, nullptr, nullptr,
                                         nullptr, nullptr, nullptr, nullptr, DD, DD);
}